// round 6
// baseline (speedup 1.0000x reference)
#include <cuda_runtime.h>
#include <math.h>
#include <stdint.h>

// ---------------- model constants ----------------
#define DMODEL 512
#define NTOK   2048
#define NWIN   16
#define WSZ    128
#define NHEAD  8
#define DHEAD  64
#define FFDIM  2048

// ---------------- scratch (no allocs allowed) ----------------
__device__ alignas(128) float g_X  [NTOK * DMODEL];
__device__ alignas(128) float g_XN [NTOK * DMODEL];
__device__ alignas(128) float g_Q  [NTOK * DMODEL];
__device__ alignas(128) float g_K  [NTOK * DMODEL];
__device__ alignas(128) float g_KVX[NTOK * 2 * DMODEL];
__device__ alignas(128) float g_H  [NTOK * FFDIM];
__device__ alignas(128) float g_AO [NTOK * DMODEL];
__device__ alignas(128) float g_G  [NWIN * DMODEL];
__device__ alignas(128) float g_GN [NWIN * DMODEL];
__device__ alignas(128) float g_QG [NWIN * DMODEL];
__device__ alignas(128) float g_KVG[NWIN * 2 * DMODEL];
__device__ alignas(128) float g_GO [NWIN * DMODEL];
__device__ alignas(128) float g_GH [NWIN * FFDIM];
__device__ alignas(128) float g_GKV[NWIN * 2 * DMODEL];
__device__ alignas(128) float g_WC [512 * 32000];   // packed tf32 weight staging

// ---------------- embedding gather ----------------
__global__ void embed_kernel(const int* __restrict__ tokens,
                             const float* __restrict__ emb,
                             float* __restrict__ X)
{
    int row = blockIdx.x;
    int d   = threadIdx.x;
    X[row * DMODEL + d] = emb[(size_t)tokens[row] * DMODEL + d];
}

// ---------------- window mean + pos emb ----------------
__global__ void winmean_kernel(const float* __restrict__ X,
                               const float* __restrict__ gpos,
                               float* __restrict__ G)
{
    int w = blockIdx.x;
    int d = threadIdx.x;
    float s = 0.f;
    for (int i = 0; i < WSZ; i++)
        s += X[(w * WSZ + i) * DMODEL + d];
    G[w * DMODEL + d] = s * (1.f / 128.f) + gpos[w * DMODEL + d];
}

// ---------------- layernorm ----------------
__global__ void ln_kernel(const float* __restrict__ in, float* __restrict__ out,
                          const float* __restrict__ w, const float* __restrict__ b)
{
    __shared__ float sh[8];
    __shared__ float stat;
    int row = blockIdx.x;
    int tid = threadIdx.x;
    const float* r = in + (size_t)row * DMODEL;
    float x0 = r[tid], x1 = r[tid + 256];

    float v = x0 + x1;
    for (int o = 16; o; o >>= 1) v += __shfl_down_sync(0xffffffffu, v, o);
    if ((tid & 31) == 0) sh[tid >> 5] = v;
    __syncthreads();
    if (tid == 0) {
        float t = 0.f;
        for (int i = 0; i < 8; i++) t += sh[i];
        stat = t * (1.f / 512.f);
    }
    __syncthreads();
    float mu = stat;
    float d0 = x0 - mu, d1 = x1 - mu;
    __syncthreads();
    v = d0 * d0 + d1 * d1;
    for (int o = 16; o; o >>= 1) v += __shfl_down_sync(0xffffffffu, v, o);
    if ((tid & 31) == 0) sh[tid >> 5] = v;
    __syncthreads();
    if (tid == 0) {
        float t = 0.f;
        for (int i = 0; i < 8; i++) t += sh[i];
        stat = t * (1.f / 512.f);
    }
    __syncthreads();
    float rstd = rsqrtf(stat + 1e-5f);
    out[(size_t)row * DMODEL + tid]       = d0 * rstd * w[tid]       + b[tid];
    out[(size_t)row * DMODEL + tid + 256] = d1 * rstd * w[tid + 256] + b[tid + 256];
}

// ---------------- tf32 helpers ----------------
__device__ __forceinline__ float to_tf32(float x)
{
    float r;
    asm("cvt.rna.tf32.f32 %0, %1;" : "=f"(r) : "f"(x));
    return r;
}

__device__ __forceinline__ void mma_tf32(float* c, const uint32_t* a, const uint32_t* b)
{
    asm volatile(
        "mma.sync.aligned.m16n8k8.row.col.f32.tf32.tf32.f32 "
        "{%0,%1,%2,%3}, {%4,%5,%6,%7}, {%8,%9}, {%0,%1,%2,%3};"
        : "+f"(c[0]), "+f"(c[1]), "+f"(c[2]), "+f"(c[3])
        : "r"(a[0]), "r"(a[1]), "r"(a[2]), "r"(a[3]), "r"(b[0]), "r"(b[1]));
}

__device__ __forceinline__ void cp_async16(uint32_t dst, const void* src)
{
    asm volatile("cp.async.ca.shared.global [%0], [%1], 16;" :: "r"(dst), "l"(src));
}
__device__ __forceinline__ void cp_commit() { asm volatile("cp.async.commit_group;"); }
__device__ __forceinline__ void cp_wait0()  { asm volatile("cp.async.wait_group 0;"); }

// ---------------- weight pack: tf32 + fragment-pair layout ----------------
// dst[g*N*8 + n*8 + 2c + hi] = tf32(src[(g*8 + c + 4*hi)*ldb + n])
// One thread per (g, n): 8 strided reads, one 32B contiguous write.
__global__ void packB_kernel(const float* __restrict__ src, float* __restrict__ dst,
                             int N, int ldb)
{
    int idx = blockIdx.x * 256 + threadIdx.x;   // g*N + n
    int g = idx / N, n = idx - g * N;
    const float* s = src + (size_t)g * 8 * ldb + n;
    float o[8];
#pragma unroll
    for (int j = 0; j < 8; j++)
        o[2 * (j & 3) + (j >> 2)] = to_tf32(s[(size_t)j * ldb]);
    float4* d = reinterpret_cast<float4*>(dst + (size_t)idx * 8);
    d[0] = make_float4(o[0], o[1], o[2], o[3]);
    d[1] = make_float4(o[4], o[5], o[6], o[7]);
}

// ---------------- tf32 tensor-core GEMM (M%128==0, N%128==0, K%16==0) ----------------
// B is PACKED (packB_kernel layout, compact width N). A fp32 row-major lda=K.
// A-smem: XOR pair layout, fragment = LDS.64.  B-smem: packed, fragment = LDS.64.
// Register double-buffered fragments hide LDS latency behind MMA batches.
#define KT 16
__global__ void __launch_bounds__(256) tf32gemm_kernel(
    const float* __restrict__ A, const float* __restrict__ B, float* __restrict__ C,
    const float* __restrict__ bias, const float* __restrict__ res,
    int M, int N, int K, int gelu_flag)
{
    __shared__ float Asw[2][2][128][8];   // [buf][g][row][slot]
    __shared__ float Bs [2][2][128][8];   // [buf][g][n][slot]

    const int tid  = threadIdx.x;
    const int lane = tid & 31, warp = tid >> 5;
    const int wm = (warp & 1) * 64;
    const int wn = (warp >> 1) * 32;
    const int crow0 = blockIdx.y * 128, ccol0 = blockIdx.x * 128;

    const int a_r = tid >> 1, a_g = tid & 1;
    const int a_r3 = a_r & 3;
    const int b_gg = tid >> 7, b_n = tid & 127;

    const float* Ag = A + (size_t)(crow0 + a_r) * K + a_g * 8;
    const float* Bg = B + ((size_t)b_gg * N + ccol0 + b_n) * 8;  // + 2*kt*N*8 per tile
    const size_t  Bstep = (size_t)2 * N * 8;

    const uint32_t bB0 = (uint32_t)__cvta_generic_to_shared(&Bs[0][b_gg][b_n][0]);
    const uint32_t bB1 = (uint32_t)__cvta_generic_to_shared(&Bs[1][b_gg][b_n][0]);

    const int r3q = (lane >> 2) & 3;
    const int so  = 2 * ((lane & 3) ^ r3q);   // A fragment slot offset
    const int bo  = 2 * (lane & 3);           // B fragment slot offset

    float acc[4][4][4];
#pragma unroll
    for (int i = 0; i < 4; i++)
#pragma unroll
        for (int j = 0; j < 4; j++)
#pragma unroll
            for (int k = 0; k < 4; k++) acc[i][j][k] = 0.f;

#define STAGEA(buf, v0, v1) do {                                                   \
    float* _d = &Asw[buf][a_g][a_r][0];                                            \
    *reinterpret_cast<float2*>(_d + 2*(0 ^ a_r3)) = make_float2(to_tf32((v0).x), to_tf32((v1).x)); \
    *reinterpret_cast<float2*>(_d + 2*(1 ^ a_r3)) = make_float2(to_tf32((v0).y), to_tf32((v1).y)); \
    *reinterpret_cast<float2*>(_d + 2*(2 ^ a_r3)) = make_float2(to_tf32((v0).z), to_tf32((v1).z)); \
    *reinterpret_cast<float2*>(_d + 2*(3 ^ a_r3)) = make_float2(to_tf32((v0).w), to_tf32((v1).w)); \
} while (0)

#define LOADF(af, bf, buf, g) do {                                                  \
    _Pragma("unroll")                                                               \
    for (int _am = 0; _am < 4; _am++) {                                             \
        int _r = wm + _am * 16 + (lane >> 2);                                       \
        float2 _p0 = *reinterpret_cast<const float2*>(&Asw[buf][g][_r][so]);        \
        float2 _p1 = *reinterpret_cast<const float2*>(&Asw[buf][g][_r + 8][so]);    \
        af[_am][0] = __float_as_uint(_p0.x); af[_am][1] = __float_as_uint(_p1.x);   \
        af[_am][2] = __float_as_uint(_p0.y); af[_am][3] = __float_as_uint(_p1.y);   \
    }                                                                               \
    _Pragma("unroll")                                                               \
    for (int _bn = 0; _bn < 4; _bn++) {                                             \
        int _cc = wn + _bn * 8 + (lane >> 2);                                       \
        float2 _bp = *reinterpret_cast<const float2*>(&Bs[buf][g][_cc][bo]);        \
        bf[_bn][0] = __float_as_uint(_bp.x); bf[_bn][1] = __float_as_uint(_bp.y);   \
    }                                                                               \
} while (0)

#define MMAF(af, bf) do {                                                           \
    _Pragma("unroll")                                                               \
    for (int _am = 0; _am < 4; _am++)                                               \
        _Pragma("unroll")                                                           \
        for (int _bn = 0; _bn < 4; _bn++)                                           \
            mma_tf32(acc[_am][_bn], af[_am], bf[_bn]);                              \
} while (0)

    const int nk = K / KT;

    // ---- stage tile 0 ----
    {
        float4 av0 = *reinterpret_cast<const float4*>(Ag);
        float4 av1 = *reinterpret_cast<const float4*>(Ag + 4);
        STAGEA(0, av0, av1);
        cp_async16(bB0,      Bg);
        cp_async16(bB0 + 16, Bg + 4);
        cp_commit();
    }
    cp_wait0();
    __syncthreads();

    uint32_t af0[4][4], bf0[4][2], af1[4][4], bf1[4][2];
    LOADF(af0, bf0, 0, 0);

    for (int kt = 0; kt < nk; kt++) {
        const int cur = kt & 1, nxt = cur ^ 1;
        const bool more = (kt + 1 < nk);

        float4 av0, av1;
        if (more) {
            const float* bsrc = Bg + (size_t)(kt + 1) * Bstep;
            uint32_t bd = nxt ? bB1 : bB0;
            cp_async16(bd,      bsrc);
            cp_async16(bd + 16, bsrc + 4);
            cp_commit();
            const float* Ap = Ag + (kt + 1) * KT;
            av0 = *reinterpret_cast<const float4*>(Ap);
            av1 = *reinterpret_cast<const float4*>(Ap + 4);
        }

        LOADF(af1, bf1, cur, 1);
        MMAF(af0, bf0);

        if (more) {
            STAGEA(nxt, av0, av1);
            cp_wait0();
            __syncthreads();
            LOADF(af0, bf0, nxt, 0);
        }
        MMAF(af1, bf1);
    }

    // ---- epilogue ----
#pragma unroll
    for (int am = 0; am < 4; am++) {
        const int r0 = crow0 + wm + am * 16 + (lane >> 2);
#pragma unroll
        for (int bn = 0; bn < 4; bn++) {
            const int c0 = ccol0 + wn + bn * 8 + (lane & 3) * 2;
            float v0 = acc[am][bn][0], v1 = acc[am][bn][1];
            float v2 = acc[am][bn][2], v3 = acc[am][bn][3];
            if (bias) {
                float b0 = bias[c0], b1 = bias[c0 + 1];
                v0 += b0; v1 += b1; v2 += b0; v3 += b1;
            }
            if (gelu_flag) {
                v0 = 0.5f * v0 * (1.f + erff(v0 * 0.70710678118654752f));
                v1 = 0.5f * v1 * (1.f + erff(v1 * 0.70710678118654752f));
                v2 = 0.5f * v2 * (1.f + erff(v2 * 0.70710678118654752f));
                v3 = 0.5f * v3 * (1.f + erff(v3 * 0.70710678118654752f));
            }
            size_t i0 = (size_t)r0 * N + c0;
            size_t i1 = (size_t)(r0 + 8) * N + c0;
            if (res) {
                v0 += res[i0]; v1 += res[i0 + 1];
                v2 += res[i1]; v3 += res[i1 + 1];
            }
            *reinterpret_cast<float2*>(C + i0) = make_float2(v0, v1);
            *reinterpret_cast<float2*>(C + i1) = make_float2(v2, v3);
        }
    }
}

// ---------------- small-M GEMM (M<=16), fp32, split-K within block ----------------
#define SG_KC 256
__global__ void __launch_bounds__(1024, 1) smallgemm_kernel(
    const float* __restrict__ A, const float* __restrict__ B, float* __restrict__ C,
    const float* __restrict__ bias, const float* __restrict__ res,
    int M, int N, int K, int ldb, int gelu_flag)
{
    __shared__ float As[2][16][SG_KC];
    __shared__ float Ps[16][128];
    const int tid  = threadIdx.x;
    const int col  = blockIdx.x * 128 + (tid & 127);
    const int grp  = tid >> 7;
    const int half = grp >> 2;
    const int rg   = grp & 3;
    const int Kh   = K >> 1;

    float acc[4] = {0.f, 0.f, 0.f, 0.f};
    const float* Bp = B + (size_t)half * Kh * ldb + col;

    for (int kc = 0; kc < Kh; kc += SG_KC) {
        for (int idx = tid; idx < 2 * 16 * SG_KC; idx += 1024) {
            int h = idx >> 12;
            int r = (idx >> 8) & 15;
            int k = idx & (SG_KC - 1);
            As[h][r][k] = (r < M) ? A[(size_t)r * K + h * Kh + kc + k] : 0.f;
        }
        __syncthreads();
#pragma unroll 1
        for (int k0 = 0; k0 < SG_KC; k0 += 16) {
            float bv[16];
#pragma unroll
            for (int u = 0; u < 16; u++)
                bv[u] = Bp[(size_t)(kc + k0 + u) * ldb];
#pragma unroll
            for (int u = 0; u < 16; u++) {
#pragma unroll
                for (int r = 0; r < 4; r++)
                    acc[r] = fmaf(As[half][rg * 4 + r][k0 + u], bv[u], acc[r]);
            }
        }
        __syncthreads();
    }

    if (half == 1) {
#pragma unroll
        for (int r = 0; r < 4; r++)
            Ps[rg * 4 + r][tid & 127] = acc[r];
    }
    __syncthreads();
    if (half == 0) {
#pragma unroll
        for (int r = 0; r < 4; r++) {
            int gr = rg * 4 + r;
            if (gr >= M) continue;
            float v = acc[r] + Ps[gr][tid & 127];
            if (bias) v += bias[col];
            if (gelu_flag) v = 0.5f * v * (1.f + erff(v * 0.70710678118654752f));
            size_t idx = (size_t)gr * N + col;
            if (res) v += res[idx];
            C[idx] = v;
        }
    }
}

// ---------------- rotary embedding ----------------
__global__ void rotary_kernel(float* __restrict__ Q, float* __restrict__ K)
{
    int i = blockIdx.x;
    int t = threadIdx.x;
    int h = t >> 5, d = t & 31;
    float inv = 1.f / powf(10000.f, (float)(2 * d) / 64.f);
    float ang = (float)i * inv;
    float s, c;
    sincosf(ang, &s, &c);
    int base = i * DMODEL + h * DHEAD + d;
    float a = Q[base], b2 = Q[base + 32];
    Q[base]      = a * c - b2 * s;
    Q[base + 32] = b2 * c + a * s;
    a = K[base]; b2 = K[base + 32];
    K[base]      = a * c - b2 * s;
    K[base + 32] = b2 * c + a * s;
}

// ---------------- global-token attention ----------------
__global__ void global_attn_kernel(const float* __restrict__ QG,
                                   const float* __restrict__ KVG,
                                   const float* __restrict__ KVX,
                                   float* __restrict__ GO)
{
    __shared__ float q[64];
    __shared__ float lg[129];
    int w = blockIdx.x, h = blockIdx.y;
    int tid = threadIdx.x;
    if (tid < 64) q[tid] = QG[w * DMODEL + h * DHEAD + tid];
    __syncthreads();
    if (tid < 129) {
        const float* kp = (tid == 0)
            ? (KVG + (size_t)w * 1024 + h * DHEAD)
            : (KVX + (size_t)(w * WSZ + tid - 1) * 1024 + h * DHEAD);
        float dt = 0.f;
#pragma unroll
        for (int d = 0; d < 64; d++) dt = fmaf(q[d], kp[d], dt);
        lg[tid] = dt * 0.125f;
    }
    __syncthreads();
    float m = -1e30f;
    for (int j = 0; j < 129; j++) m = fmaxf(m, lg[j]);
    float s = 0.f;
    for (int j = 0; j < 129; j++) s += expf(lg[j] - m);
    if (tid < 64) {
        float acc = 0.f;
        for (int j = 0; j < 129; j++) {
            float p = expf(lg[j] - m);
            float v = (j == 0)
                ? KVG[(size_t)w * 1024 + 512 + h * DHEAD + tid]
                : KVX[(size_t)(w * WSZ + j - 1) * 1024 + 512 + h * DHEAD + tid];
            acc = fmaf(p, v, acc);
        }
        GO[w * DMODEL + h * DHEAD + tid] = acc / s;
    }
}

// ---------------- local windowed attention (online softmax) ----------------
__global__ void local_attn_kernel(const float* __restrict__ Q,
                                  const float* __restrict__ K,
                                  const float* __restrict__ GKV,
                                  float* __restrict__ AO)
{
    extern __shared__ float sm[];
    float* sk  = sm;                 // [271][64]
    float* sgv = sm + 271 * 64;      // [15][64]
    int w = blockIdx.x, h = blockIdx.y;
    int tid = threadIdx.x;           // 128

    for (int idx = tid; idx < 15 * 64; idx += 128) {
        int j = idx >> 6, d = idx & 63;
        sk[idx]  = GKV[(size_t)j * 1024 + h * DHEAD + d];
        sgv[idx] = GKV[(size_t)j * 1024 + 512 + h * DHEAD + d];
    }
    for (int idx = tid; idx < 256 * 64; idx += 128) {
        int c = idx >> 6, d = idx & 63;
        int t = (w - 1) * WSZ + c;
        sk[15 * 64 + idx] = (t >= 0) ? K[(size_t)t * DMODEL + h * DHEAD + d] : 0.f;
    }
    __syncthreads();

    const int i = tid;
    float q[64];
    const float* qp = Q + (size_t)(w * WSZ + i) * DMODEL + h * DHEAD;
#pragma unroll
    for (int d = 0; d < 64; d++) q[d] = qp[d];

    const int jend = 15 + i + 128;

    float m = -1e30f, s = 0.f;
    float acc[64];
#pragma unroll
    for (int d = 0; d < 64; d++) acc[d] = 0.f;

    // global keys (values = sgv)
    for (int j = 0; j < w; j++) {
        const float* kp = sk + j * 64;
        float dt = 0.f;
#pragma unroll
        for (int d = 0; d < 64; d++) dt = fmaf(q[d], kp[d], dt);
        dt *= 0.125f;
        float e;
        if (dt > m) {
            float sc = expf(m - dt);
            s *= sc;
#pragma unroll
            for (int d = 0; d < 64; d++) acc[d] *= sc;
            m = dt; e = 1.f;
        } else {
            e = expf(dt - m);
        }
        s += e;
        const float* vp = sgv + j * 64;
#pragma unroll
        for (int d = 0; d < 64; d++) acc[d] = fmaf(e, vp[d], acc[d]);
    }
    // windowed keys (values = keys)
    for (int j = 15; j <= jend; j++) {
        const float* kp = sk + j * 64;
        float dt = 0.f;
#pragma unroll
        for (int d = 0; d < 64; d++) dt = fmaf(q[d], kp[d], dt);
        dt *= 0.125f;
        float e;
        if (dt > m) {
            float sc = expf(m - dt);
            s *= sc;
#pragma unroll
            for (int d = 0; d < 64; d++) acc[d] *= sc;
            m = dt; e = 1.f;
        } else {
            e = expf(dt - m);
        }
        s += e;
#pragma unroll
        for (int d = 0; d < 64; d++) acc[d] = fmaf(e, kp[d], acc[d]);
    }
    float inv = 1.f / s;
    float* op = AO + (size_t)(w * WSZ + i) * DMODEL + h * DHEAD;
#pragma unroll
    for (int d = 0; d < 64; d++) op[d] = acc[d] * inv;
}

// ---------------- host orchestration ----------------
static inline dim3 gg(int M, int N) { return dim3(N / 128, (M + 127) / 128); }

extern "C" void kernel_launch(void* const* d_in, const int* in_sizes, int n_in,
                              void* d_out, int out_size)
{
    const int*   tokens     = (const int*)  d_in[0];
    const float* tok_emb    = (const float*)d_in[1];
    const float* gpos_emb   = (const float*)d_in[2];
    const float* g_norm_w   = (const float*)d_in[3];
    const float* g_norm_b   = (const float*)d_in[4];
    const float* g_Wq       = (const float*)d_in[5];
    const float* g_Wkv      = (const float*)d_in[6];
    const float* g_Wo       = (const float*)d_in[7];
    const float* g_bo       = (const float*)d_in[8];
    const float* gff_norm_w = (const float*)d_in[9];
    const float* gff_norm_b = (const float*)d_in[10];
    const float* gff_W1     = (const float*)d_in[11];
    const float* gff_b1     = (const float*)d_in[12];
    const float* gff_W2     = (const float*)d_in[13];
    const float* gff_b2     = (const float*)d_in[14];
    const float* la_norm_w  = (const float*)d_in[15];
    const float* la_norm_b  = (const float*)d_in[16];
    const float* la_Wq      = (const float*)d_in[17];
    const float* la_Wkv     = (const float*)d_in[18];
    const float* la_Wo      = (const float*)d_in[19];
    const float* la_bo      = (const float*)d_in[20];
    const float* lff_norm_w = (const float*)d_in[21];
    const float* lff_norm_b = (const float*)d_in[22];
    const float* lff_W1     = (const float*)d_in[23];
    const float* lff_b1     = (const float*)d_in[24];
    const float* lff_W2     = (const float*)d_in[25];
    const float* lff_b2     = (const float*)d_in[26];
    const float* out_norm_w = (const float*)d_in[27];
    const float* out_norm_b = (const float*)d_in[28];
    const float* out_W      = (const float*)d_in[29];
    const float* out_b      = (const float*)d_in[30];

    float *X, *XN, *Q, *K, *KVX, *H, *AO, *G, *GN, *QG, *KVG, *GO, *GH, *GKV, *WC;
    cudaGetSymbolAddress((void**)&X,   g_X);
    cudaGetSymbolAddress((void**)&XN,  g_XN);
    cudaGetSymbolAddress((void**)&Q,   g_Q);
    cudaGetSymbolAddress((void**)&K,   g_K);
    cudaGetSymbolAddress((void**)&KVX, g_KVX);
    cudaGetSymbolAddress((void**)&H,   g_H);
    cudaGetSymbolAddress((void**)&AO,  g_AO);
    cudaGetSymbolAddress((void**)&G,   g_G);
    cudaGetSymbolAddress((void**)&GN,  g_GN);
    cudaGetSymbolAddress((void**)&QG,  g_QG);
    cudaGetSymbolAddress((void**)&KVG, g_KVG);
    cudaGetSymbolAddress((void**)&GO,  g_GO);
    cudaGetSymbolAddress((void**)&GH,  g_GH);
    cudaGetSymbolAddress((void**)&GKV, g_GKV);
    cudaGetSymbolAddress((void**)&WC,  g_WC);

    cudaFuncSetAttribute(local_attn_kernel,
                         cudaFuncAttributeMaxDynamicSharedMemorySize, 73216);

    // packed-weight region pointers (disjoint slices of g_WC, reused per layer)
    float* WC_kvx = WC;                    // 512*1024
    float* WC_q   = WC + 512 * 1024;       // 512*512
    float* WC_kv  = WC + 512 * 1536;       // 512*512 (K-projection half)
    float* WC_wo  = WC + 512 * 2560;       // 512*512
    float* WC_ff1 = WC + 512 * 3072;       // 512*2048
    float* WC_ff2 = WC + 512 * 5120;       // 2048*512

#define PK(dst, src, K_, N_, ldb_) \
    packB_kernel<<<((K_) / 8) * (N_) / 256, 256>>>((const float*)(src), (float*)(dst), (N_), (ldb_))

    embed_kernel<<<NTOK, DMODEL>>>(tokens, tok_emb, X);
    winmean_kernel<<<NWIN, DMODEL>>>(X, gpos_emb, G);
    PK(WC_kvx, g_Wkv, 512, 1024, 1024);    // shared across layers, packed once

    for (int l = 0; l < 2; l++) {
        // ---- global-token transformer (shared weights) ----
        ln_kernel<<<NWIN, 256>>>(G, GN, g_norm_w, g_norm_b);
        tf32gemm_kernel<<<gg(2048, 1024), 256>>>(X, WC_kvx, KVX, nullptr, nullptr, 2048, 1024, 512, 0);
        smallgemm_kernel<<<4,  1024>>>(GN, g_Wq,  QG,  nullptr, nullptr, 16, 512,  512, 512,  0);
        smallgemm_kernel<<<8,  1024>>>(GN, g_Wkv, KVG, nullptr, nullptr, 16, 1024, 512, 1024, 0);
        global_attn_kernel<<<dim3(16, 8), 256>>>(QG, KVG, KVX, GO);
        smallgemm_kernel<<<4,  1024>>>(GO, g_Wo, G, g_bo, G, 16, 512, 512, 512, 0);
        ln_kernel<<<NWIN, 256>>>(G, GN, gff_norm_w, gff_norm_b);
        smallgemm_kernel<<<16, 1024>>>(GN, gff_W1, GH, gff_b1, nullptr, 16, 2048, 512,  2048, 1);
        smallgemm_kernel<<<4,  1024>>>(GH, gff_W2, G,  gff_b2, G,       16, 512,  2048, 512,  0);

        // ---- local windowed attention ----
        PK(WC_q,  la_Wq  + (size_t)l * 512 * 512,  512, 512, 512);
        PK(WC_kv, la_Wkv + (size_t)l * 512 * 1024, 512, 512, 1024);
        PK(WC_wo, la_Wo  + (size_t)l * 512 * 512,  512, 512, 512);
        ln_kernel<<<NTOK, 256>>>(X, XN, la_norm_w + l * 512, la_norm_b + l * 512);
        tf32gemm_kernel<<<gg(2048, 512), 256>>>(XN, WC_q,  Q, nullptr, nullptr, 2048, 512, 512, 0);
        tf32gemm_kernel<<<gg(2048, 512), 256>>>(XN, WC_kv, K, nullptr, nullptr, 2048, 512, 512, 0);
        smallgemm_kernel<<<8, 1024>>>(G, la_Wkv + (size_t)l * 512 * 1024, GKV, nullptr, nullptr, 15, 1024, 512, 1024, 0);
        rotary_kernel<<<NTOK, 256>>>(Q, K);
        local_attn_kernel<<<dim3(16, 8), 128, 73216>>>(Q, K, GKV, AO);
        tf32gemm_kernel<<<gg(2048, 512), 256>>>(AO, WC_wo, X, la_bo + l * 512, X, 2048, 512, 512, 0);

        // ---- local FF ----
        PK(WC_ff1, lff_W1 + (size_t)l * 512 * 2048, 512, 2048, 2048);
        PK(WC_ff2, lff_W2 + (size_t)l * 2048 * 512, 2048, 512, 512);
        ln_kernel<<<NTOK, 256>>>(X, XN, lff_norm_w + l * 512, lff_norm_b + l * 512);
        tf32gemm_kernel<<<gg(2048, 2048), 256>>>(XN, WC_ff1, H, lff_b1 + l * 2048, nullptr, 2048, 2048, 512,  1);
        tf32gemm_kernel<<<gg(2048, 512),  256>>>(H,  WC_ff2, X, lff_b2 + l * 512,  X,       2048, 512,  2048, 0);
    }

    // ---- output head ----
    PK(WC, out_W, 512, 32000, 32000);
    ln_kernel<<<NTOK, 256>>>(X, XN, out_norm_w, out_norm_b);
    tf32gemm_kernel<<<gg(2048, 32000), 256>>>(XN, WC, (float*)d_out, out_b, nullptr,
                                              2048, 32000, 512, 0);
}

// round 7
// speedup vs baseline: 1.1530x; 1.1530x over previous
#include <cuda_runtime.h>
#include <math.h>
#include <stdint.h>

// ---------------- model constants ----------------
#define DMODEL 512
#define NTOK   2048
#define NWIN   16
#define WSZ    128
#define NHEAD  8
#define DHEAD  64
#define FFDIM  2048

// ---------------- scratch (no allocs allowed) ----------------
__device__ alignas(128) float g_X  [NTOK * DMODEL];
__device__ alignas(128) float g_XN [NTOK * DMODEL];
__device__ alignas(128) float g_Q  [NTOK * DMODEL];
__device__ alignas(128) float g_K  [NTOK * DMODEL];
__device__ alignas(128) float g_KVX[NTOK * 2 * DMODEL];
__device__ alignas(128) float g_H  [NTOK * FFDIM];
__device__ alignas(128) float g_AO [NTOK * DMODEL];
__device__ alignas(128) float g_G  [NWIN * DMODEL];
__device__ alignas(128) float g_GN [NWIN * DMODEL];
__device__ alignas(128) float g_QG [NWIN * DMODEL];
__device__ alignas(128) float g_KVG[NWIN * 2 * DMODEL];
__device__ alignas(128) float g_GO [NWIN * DMODEL];
__device__ alignas(128) float g_GH [NWIN * FFDIM];
__device__ alignas(128) float g_GKV[NWIN * 2 * DMODEL];
__device__ alignas(128) float g_WC [512 * 32000];   // tf32-converted weight staging

// ---------------- embedding gather ----------------
__global__ void embed_kernel(const int* __restrict__ tokens,
                             const float* __restrict__ emb,
                             float* __restrict__ X)
{
    int row = blockIdx.x;
    int d   = threadIdx.x;
    X[row * DMODEL + d] = emb[(size_t)tokens[row] * DMODEL + d];
}

// ---------------- window mean + pos emb ----------------
__global__ void winmean_kernel(const float* __restrict__ X,
                               const float* __restrict__ gpos,
                               float* __restrict__ G)
{
    int w = blockIdx.x;
    int d = threadIdx.x;
    float s = 0.f;
    for (int i = 0; i < WSZ; i++)
        s += X[(w * WSZ + i) * DMODEL + d];
    G[w * DMODEL + d] = s * (1.f / 128.f) + gpos[w * DMODEL + d];
}

// ---------------- layernorm ----------------
__global__ void ln_kernel(const float* __restrict__ in, float* __restrict__ out,
                          const float* __restrict__ w, const float* __restrict__ b)
{
    __shared__ float sh[8];
    __shared__ float stat;
    int row = blockIdx.x;
    int tid = threadIdx.x;
    const float* r = in + (size_t)row * DMODEL;
    float x0 = r[tid], x1 = r[tid + 256];

    float v = x0 + x1;
    for (int o = 16; o; o >>= 1) v += __shfl_down_sync(0xffffffffu, v, o);
    if ((tid & 31) == 0) sh[tid >> 5] = v;
    __syncthreads();
    if (tid == 0) {
        float t = 0.f;
        for (int i = 0; i < 8; i++) t += sh[i];
        stat = t * (1.f / 512.f);
    }
    __syncthreads();
    float mu = stat;
    float d0 = x0 - mu, d1 = x1 - mu;
    __syncthreads();
    v = d0 * d0 + d1 * d1;
    for (int o = 16; o; o >>= 1) v += __shfl_down_sync(0xffffffffu, v, o);
    if ((tid & 31) == 0) sh[tid >> 5] = v;
    __syncthreads();
    if (tid == 0) {
        float t = 0.f;
        for (int i = 0; i < 8; i++) t += sh[i];
        stat = t * (1.f / 512.f);
    }
    __syncthreads();
    float rstd = rsqrtf(stat + 1e-5f);
    out[(size_t)row * DMODEL + tid]       = d0 * rstd * w[tid]       + b[tid];
    out[(size_t)row * DMODEL + tid + 256] = d1 * rstd * w[tid + 256] + b[tid + 256];
}

// ---------------- tf32 helpers ----------------
__device__ __forceinline__ float to_tf32(float x)
{
    float r;
    asm("cvt.rna.tf32.f32 %0, %1;" : "=f"(r) : "f"(x));
    return r;
}

__device__ __forceinline__ void mma_tf32(float* c, const uint32_t* a, const uint32_t* b)
{
    asm volatile(
        "mma.sync.aligned.m16n8k8.row.col.f32.tf32.tf32.f32 "
        "{%0,%1,%2,%3}, {%4,%5,%6,%7}, {%8,%9}, {%0,%1,%2,%3};"
        : "+f"(c[0]), "+f"(c[1]), "+f"(c[2]), "+f"(c[3])
        : "r"(a[0]), "r"(a[1]), "r"(a[2]), "r"(a[3]), "r"(b[0]), "r"(b[1]));
}

__device__ __forceinline__ void cp_async16(uint32_t dst, const void* src)
{
    asm volatile("cp.async.ca.shared.global [%0], [%1], 16;" :: "r"(dst), "l"(src));
}
__device__ __forceinline__ void cp_commit() { asm volatile("cp.async.commit_group;"); }
__device__ __forceinline__ void cp_wait0()  { asm volatile("cp.async.wait_group 0;"); }
__device__ __forceinline__ void cp_wait1()  { asm volatile("cp.async.wait_group 1;"); }

// ---------------- weight tf32 pre-convert (elementwise, n % 1024 == 0) ----------------
__global__ void tf32cvt_kernel(const float4* __restrict__ src, float4* __restrict__ dst)
{
    int i = blockIdx.x * 256 + threadIdx.x;
    float4 v = src[i];
    dst[i] = make_float4(to_tf32(v.x), to_tf32(v.y), to_tf32(v.z), to_tf32(v.w));
}

// ---------------- tf32 tensor-core GEMM (M%128==0, N%128==0, K%16==0) ----------------
// B pre-converted to tf32. A fp32, cvt'd in staging (XOR store addresses).
// 3-stage cp.async ring for B; 2-deep register prefetch for A.
#define KT 16
#define SMS 136
__global__ void __launch_bounds__(256, 2) tf32gemm_kernel(
    const float* __restrict__ A, const float* __restrict__ B, float* __restrict__ C,
    const float* __restrict__ bias, const float* __restrict__ res,
    int M, int N, int K, int ldb, int gelu_flag)
{
    __shared__ float Asw[2][2][128][8];   // [buf][g][row][slot]
    __shared__ float Bs[3][KT][SMS];      // [stage][k][n]

    const int tid  = threadIdx.x;
    const int lane = tid & 31, warp = tid >> 5;
    const int wm = (warp & 1) * 64;
    const int wn = (warp >> 1) * 32;
    const int crow0 = blockIdx.y * 128, ccol0 = blockIdx.x * 128;

    const int a_r = tid >> 1, a_g = tid & 1;
    const int a_r3 = a_r & 3;
    const int b_r = tid >> 4, b_c = (tid & 15) * 8;

    const float* Ag = A + (size_t)(crow0 + a_r) * K + a_g * 8;
    const float* Bg = B + (size_t)b_r * ldb + ccol0 + b_c;

    uint32_t bsa[3];
    bsa[0] = (uint32_t)__cvta_generic_to_shared(&Bs[0][b_r][b_c]);
    bsa[1] = (uint32_t)__cvta_generic_to_shared(&Bs[1][b_r][b_c]);
    bsa[2] = (uint32_t)__cvta_generic_to_shared(&Bs[2][b_r][b_c]);

    const int r3q = (lane >> 2) & 3;
    const int so  = 2 * ((lane & 3) ^ r3q);

    float acc[4][4][4];
#pragma unroll
    for (int i = 0; i < 4; i++)
#pragma unroll
        for (int j = 0; j < 4; j++)
#pragma unroll
            for (int k = 0; k < 4; k++) acc[i][j][k] = 0.f;

#define STAGEA(buf, v0, v1) do {                                                   \
    float* _d = &Asw[buf][a_g][a_r][0];                                            \
    *reinterpret_cast<float2*>(_d + 2*(0 ^ a_r3)) = make_float2(to_tf32((v0).x), to_tf32((v1).x)); \
    *reinterpret_cast<float2*>(_d + 2*(1 ^ a_r3)) = make_float2(to_tf32((v0).y), to_tf32((v1).y)); \
    *reinterpret_cast<float2*>(_d + 2*(2 ^ a_r3)) = make_float2(to_tf32((v0).z), to_tf32((v1).z)); \
    *reinterpret_cast<float2*>(_d + 2*(3 ^ a_r3)) = make_float2(to_tf32((v0).w), to_tf32((v1).w)); \
} while (0)

    const int nk = K / KT;   // >= 2 at all call sites (K = 512 or 2048)

    // ---- preamble: stage tile 0; prefetch A[1],A[2] (regs) and B[1] (smem) ----
    {
        float4 v0 = *reinterpret_cast<const float4*>(Ag);
        float4 v1 = *reinterpret_cast<const float4*>(Ag + 4);
        STAGEA(0, v0, v1);
        cp_async16(bsa[0],      Bg);
        cp_async16(bsa[0] + 16, Bg + 4);
        cp_commit();
    }
    float4 aA0, aA1, aB0, aB1;
    {
        const float* Ap = Ag + KT;
        aA0 = *reinterpret_cast<const float4*>(Ap);
        aA1 = *reinterpret_cast<const float4*>(Ap + 4);
        const float* Bp = Bg + (size_t)KT * ldb;
        cp_async16(bsa[1],      Bp);
        cp_async16(bsa[1] + 16, Bp + 4);
        cp_commit();
    }
    if (nk > 2) {
        const float* Ap = Ag + 2 * KT;
        aB0 = *reinterpret_cast<const float4*>(Ap);
        aB1 = *reinterpret_cast<const float4*>(Ap + 4);
    }
    cp_wait1();          // B[0] complete (B[1] may be in flight)
    __syncthreads();

    for (int kt = 0; kt < nk; kt++) {
        const int cur = kt & 1;
        const int s   = kt % 3;

        if (kt + 2 < nk) {
            const float* Bp = Bg + (size_t)(kt + 2) * KT * ldb;
            uint32_t bd = bsa[(kt + 2) % 3];
            cp_async16(bd,      Bp);
            cp_async16(bd + 16, Bp + 4);
            cp_commit();
        }

#pragma unroll
        for (int kk = 0; kk < KT; kk += 8) {
            const int g = kk >> 3;
            uint32_t af[4][4], bf[4][2];
            const int kc = kk + (lane & 3);
#pragma unroll
            for (int am = 0; am < 4; am++) {
                const int r = wm + am * 16 + (lane >> 2);
                float2 p0 = *reinterpret_cast<const float2*>(&Asw[cur][g][r][so]);
                float2 p1 = *reinterpret_cast<const float2*>(&Asw[cur][g][r + 8][so]);
                af[am][0] = __float_as_uint(p0.x);
                af[am][1] = __float_as_uint(p1.x);
                af[am][2] = __float_as_uint(p0.y);
                af[am][3] = __float_as_uint(p1.y);
            }
#pragma unroll
            for (int bn = 0; bn < 4; bn++) {
                const int cc = wn + bn * 8 + (lane >> 2);
                bf[bn][0] = __float_as_uint(Bs[s][kc][cc]);
                bf[bn][1] = __float_as_uint(Bs[s][kc + 4][cc]);
            }
#pragma unroll
            for (int am = 0; am < 4; am++)
#pragma unroll
                for (int bn = 0; bn < 4; bn++)
                    mma_tf32(acc[am][bn], af[am], bf[bn]);
        }

        if (kt + 1 < nk) {
            STAGEA(cur ^ 1, aA0, aA1);
            aA0 = aB0; aA1 = aB1;
            if (kt + 3 < nk) {
                const float* Ap = Ag + (kt + 3) * KT;
                aB0 = *reinterpret_cast<const float4*>(Ap);
                aB1 = *reinterpret_cast<const float4*>(Ap + 4);
            }
            if (kt + 2 < nk) cp_wait1(); else cp_wait0();
            __syncthreads();
        }
    }

    // ---- epilogue ----
#pragma unroll
    for (int am = 0; am < 4; am++) {
        const int r0 = crow0 + wm + am * 16 + (lane >> 2);
#pragma unroll
        for (int bn = 0; bn < 4; bn++) {
            const int c0 = ccol0 + wn + bn * 8 + (lane & 3) * 2;
            float v0 = acc[am][bn][0], v1 = acc[am][bn][1];
            float v2 = acc[am][bn][2], v3 = acc[am][bn][3];
            if (bias) {
                float b0 = bias[c0], b1 = bias[c0 + 1];
                v0 += b0; v1 += b1; v2 += b0; v3 += b1;
            }
            if (gelu_flag) {
                v0 = 0.5f * v0 * (1.f + erff(v0 * 0.70710678118654752f));
                v1 = 0.5f * v1 * (1.f + erff(v1 * 0.70710678118654752f));
                v2 = 0.5f * v2 * (1.f + erff(v2 * 0.70710678118654752f));
                v3 = 0.5f * v3 * (1.f + erff(v3 * 0.70710678118654752f));
            }
            size_t i0 = (size_t)r0 * N + c0;
            size_t i1 = (size_t)(r0 + 8) * N + c0;
            if (res) {
                v0 += res[i0]; v1 += res[i0 + 1];
                v2 += res[i1]; v3 += res[i1 + 1];
            }
            *reinterpret_cast<float2*>(C + i0) = make_float2(v0, v1);
            *reinterpret_cast<float2*>(C + i1) = make_float2(v2, v3);
        }
    }
}

// ---------------- small-M GEMM (M<=16), fp32, split-K within block ----------------
#define SG_KC 256
__global__ void __launch_bounds__(1024, 1) smallgemm_kernel(
    const float* __restrict__ A, const float* __restrict__ B, float* __restrict__ C,
    const float* __restrict__ bias, const float* __restrict__ res,
    int M, int N, int K, int ldb, int gelu_flag)
{
    __shared__ float As[2][16][SG_KC];
    __shared__ float Ps[16][128];
    const int tid  = threadIdx.x;
    const int col  = blockIdx.x * 128 + (tid & 127);
    const int grp  = tid >> 7;
    const int half = grp >> 2;
    const int rg   = grp & 3;
    const int Kh   = K >> 1;

    float acc[4] = {0.f, 0.f, 0.f, 0.f};
    const float* Bp = B + (size_t)half * Kh * ldb + col;

    for (int kc = 0; kc < Kh; kc += SG_KC) {
        for (int idx = tid; idx < 2 * 16 * SG_KC; idx += 1024) {
            int h = idx >> 12;
            int r = (idx >> 8) & 15;
            int k = idx & (SG_KC - 1);
            As[h][r][k] = (r < M) ? A[(size_t)r * K + h * Kh + kc + k] : 0.f;
        }
        __syncthreads();
#pragma unroll 1
        for (int k0 = 0; k0 < SG_KC; k0 += 16) {
            float bv[16];
#pragma unroll
            for (int u = 0; u < 16; u++)
                bv[u] = Bp[(size_t)(kc + k0 + u) * ldb];
#pragma unroll
            for (int u = 0; u < 16; u++) {
#pragma unroll
                for (int r = 0; r < 4; r++)
                    acc[r] = fmaf(As[half][rg * 4 + r][k0 + u], bv[u], acc[r]);
            }
        }
        __syncthreads();
    }

    if (half == 1) {
#pragma unroll
        for (int r = 0; r < 4; r++)
            Ps[rg * 4 + r][tid & 127] = acc[r];
    }
    __syncthreads();
    if (half == 0) {
#pragma unroll
        for (int r = 0; r < 4; r++) {
            int gr = rg * 4 + r;
            if (gr >= M) continue;
            float v = acc[r] + Ps[gr][tid & 127];
            if (bias) v += bias[col];
            if (gelu_flag) v = 0.5f * v * (1.f + erff(v * 0.70710678118654752f));
            size_t idx = (size_t)gr * N + col;
            if (res) v += res[idx];
            C[idx] = v;
        }
    }
}

// ---------------- rotary embedding ----------------
__global__ void rotary_kernel(float* __restrict__ Q, float* __restrict__ K)
{
    int i = blockIdx.x;
    int t = threadIdx.x;
    int h = t >> 5, d = t & 31;
    float inv = 1.f / powf(10000.f, (float)(2 * d) / 64.f);
    float ang = (float)i * inv;
    float s, c;
    sincosf(ang, &s, &c);
    int base = i * DMODEL + h * DHEAD + d;
    float a = Q[base], b2 = Q[base + 32];
    Q[base]      = a * c - b2 * s;
    Q[base + 32] = b2 * c + a * s;
    a = K[base]; b2 = K[base + 32];
    K[base]      = a * c - b2 * s;
    K[base + 32] = b2 * c + a * s;
}

// ---------------- global-token attention ----------------
__global__ void global_attn_kernel(const float* __restrict__ QG,
                                   const float* __restrict__ KVG,
                                   const float* __restrict__ KVX,
                                   float* __restrict__ GO)
{
    __shared__ float q[64];
    __shared__ float lg[129];
    int w = blockIdx.x, h = blockIdx.y;
    int tid = threadIdx.x;
    if (tid < 64) q[tid] = QG[w * DMODEL + h * DHEAD + tid];
    __syncthreads();
    if (tid < 129) {
        const float* kp = (tid == 0)
            ? (KVG + (size_t)w * 1024 + h * DHEAD)
            : (KVX + (size_t)(w * WSZ + tid - 1) * 1024 + h * DHEAD);
        float dt = 0.f;
#pragma unroll
        for (int d = 0; d < 64; d++) dt = fmaf(q[d], kp[d], dt);
        lg[tid] = dt * 0.125f;
    }
    __syncthreads();
    float m = -1e30f;
    for (int j = 0; j < 129; j++) m = fmaxf(m, lg[j]);
    float s = 0.f;
    for (int j = 0; j < 129; j++) s += expf(lg[j] - m);
    if (tid < 64) {
        float acc = 0.f;
        for (int j = 0; j < 129; j++) {
            float p = expf(lg[j] - m);
            float v = (j == 0)
                ? KVG[(size_t)w * 1024 + 512 + h * DHEAD + tid]
                : KVX[(size_t)(w * WSZ + j - 1) * 1024 + 512 + h * DHEAD + tid];
            acc = fmaf(p, v, acc);
        }
        GO[w * DMODEL + h * DHEAD + tid] = acc / s;
    }
}

// ---------------- local windowed attention (two-pass) ----------------
__global__ void local_attn_kernel(const float* __restrict__ Q,
                                  const float* __restrict__ K,
                                  const float* __restrict__ GKV,
                                  float* __restrict__ AO)
{
    extern __shared__ float sm[];
    float* sk  = sm;                 // [271][64]
    float* sgv = sm + 271 * 64;      // [15][64]
    int w = blockIdx.x, h = blockIdx.y;
    int tid = threadIdx.x;           // 128

    for (int idx = tid; idx < 15 * 64; idx += 128) {
        int j = idx >> 6, d = idx & 63;
        sk[idx]  = GKV[(size_t)j * 1024 + h * DHEAD + d];
        sgv[idx] = GKV[(size_t)j * 1024 + 512 + h * DHEAD + d];
    }
    for (int idx = tid; idx < 256 * 64; idx += 128) {
        int c = idx >> 6, d = idx & 63;
        int t = (w - 1) * WSZ + c;
        sk[15 * 64 + idx] = (t >= 0) ? K[(size_t)t * DMODEL + h * DHEAD + d] : 0.f;
    }
    __syncthreads();

    const int i = tid;
    float q[64];
    const float* qp = Q + (size_t)(w * WSZ + i) * DMODEL + h * DHEAD;
#pragma unroll
    for (int d = 0; d < 64; d++) q[d] = qp[d];

    const int jend = 15 + i + 128;

    float m = -1e30f;
    for (int j = 0; j < w; j++) {
        const float* kp = sk + j * 64;
        float dt = 0.f;
#pragma unroll
        for (int d = 0; d < 64; d++) dt = fmaf(q[d], kp[d], dt);
        m = fmaxf(m, dt * 0.125f);
    }
    for (int j = 15; j <= jend; j++) {
        const float* kp = sk + j * 64;
        float dt = 0.f;
#pragma unroll
        for (int d = 0; d < 64; d++) dt = fmaf(q[d], kp[d], dt);
        m = fmaxf(m, dt * 0.125f);
    }

    float s = 0.f;
    float acc[64];
#pragma unroll
    for (int d = 0; d < 64; d++) acc[d] = 0.f;
    for (int j = 0; j < w; j++) {
        const float* kp = sk + j * 64;
        float dt = 0.f;
#pragma unroll
        for (int d = 0; d < 64; d++) dt = fmaf(q[d], kp[d], dt);
        float e = expf(dt * 0.125f - m);
        s += e;
        const float* vp = sgv + j * 64;
#pragma unroll
        for (int d = 0; d < 64; d++) acc[d] = fmaf(e, vp[d], acc[d]);
    }
    for (int j = 15; j <= jend; j++) {
        const float* kp = sk + j * 64;
        float dt = 0.f;
#pragma unroll
        for (int d = 0; d < 64; d++) dt = fmaf(q[d], kp[d], dt);
        float e = expf(dt * 0.125f - m);
        s += e;
#pragma unroll
        for (int d = 0; d < 64; d++) acc[d] = fmaf(e, kp[d], acc[d]);
    }
    float inv = 1.f / s;
    float* op = AO + (size_t)(w * WSZ + i) * DMODEL + h * DHEAD;
#pragma unroll
    for (int d = 0; d < 64; d++) op[d] = acc[d] * inv;
}

// ---------------- host orchestration ----------------
static inline dim3 gg(int M, int N) { return dim3(N / 128, (M + 127) / 128); }

extern "C" void kernel_launch(void* const* d_in, const int* in_sizes, int n_in,
                              void* d_out, int out_size)
{
    const int*   tokens     = (const int*)  d_in[0];
    const float* tok_emb    = (const float*)d_in[1];
    const float* gpos_emb   = (const float*)d_in[2];
    const float* g_norm_w   = (const float*)d_in[3];
    const float* g_norm_b   = (const float*)d_in[4];
    const float* g_Wq       = (const float*)d_in[5];
    const float* g_Wkv      = (const float*)d_in[6];
    const float* g_Wo       = (const float*)d_in[7];
    const float* g_bo       = (const float*)d_in[8];
    const float* gff_norm_w = (const float*)d_in[9];
    const float* gff_norm_b = (const float*)d_in[10];
    const float* gff_W1     = (const float*)d_in[11];
    const float* gff_b1     = (const float*)d_in[12];
    const float* gff_W2     = (const float*)d_in[13];
    const float* gff_b2     = (const float*)d_in[14];
    const float* la_norm_w  = (const float*)d_in[15];
    const float* la_norm_b  = (const float*)d_in[16];
    const float* la_Wq      = (const float*)d_in[17];
    const float* la_Wkv     = (const float*)d_in[18];
    const float* la_Wo      = (const float*)d_in[19];
    const float* la_bo      = (const float*)d_in[20];
    const float* lff_norm_w = (const float*)d_in[21];
    const float* lff_norm_b = (const float*)d_in[22];
    const float* lff_W1     = (const float*)d_in[23];
    const float* lff_b1     = (const float*)d_in[24];
    const float* lff_W2     = (const float*)d_in[25];
    const float* lff_b2     = (const float*)d_in[26];
    const float* out_norm_w = (const float*)d_in[27];
    const float* out_norm_b = (const float*)d_in[28];
    const float* out_W      = (const float*)d_in[29];
    const float* out_b      = (const float*)d_in[30];

    float *X, *XN, *Q, *K, *KVX, *H, *AO, *G, *GN, *QG, *KVG, *GO, *GH, *GKV, *WC;
    cudaGetSymbolAddress((void**)&X,   g_X);
    cudaGetSymbolAddress((void**)&XN,  g_XN);
    cudaGetSymbolAddress((void**)&Q,   g_Q);
    cudaGetSymbolAddress((void**)&K,   g_K);
    cudaGetSymbolAddress((void**)&KVX, g_KVX);
    cudaGetSymbolAddress((void**)&H,   g_H);
    cudaGetSymbolAddress((void**)&AO,  g_AO);
    cudaGetSymbolAddress((void**)&G,   g_G);
    cudaGetSymbolAddress((void**)&GN,  g_GN);
    cudaGetSymbolAddress((void**)&QG,  g_QG);
    cudaGetSymbolAddress((void**)&KVG, g_KVG);
    cudaGetSymbolAddress((void**)&GO,  g_GO);
    cudaGetSymbolAddress((void**)&GH,  g_GH);
    cudaGetSymbolAddress((void**)&GKV, g_GKV);
    cudaGetSymbolAddress((void**)&WC,  g_WC);

    cudaFuncSetAttribute(local_attn_kernel,
                         cudaFuncAttributeMaxDynamicSharedMemorySize, 73216);

    float* WC_kvx = WC;                    // 512*1024
    float* WC_q   = WC + 512 * 1024;       // 512*512
    float* WC_kv  = WC + 512 * 1536;       // 512*1024
    float* WC_wo  = WC + 512 * 2560;       // 512*512
    float* WC_ff1 = WC + 512 * 3072;       // 512*2048
    float* WC_ff2 = WC + 512 * 5120;       // 2048*512

#define CVT(dst, src, n) tf32cvt_kernel<<<(n) / 1024, 256>>>((const float4*)(src), (float4*)(dst))

    embed_kernel<<<NTOK, DMODEL>>>(tokens, tok_emb, X);
    winmean_kernel<<<NWIN, DMODEL>>>(X, gpos_emb, G);
    CVT(WC_kvx, g_Wkv, 512 * 1024);        // shared across layers, converted once

    for (int l = 0; l < 2; l++) {
        // ---- global-token transformer (shared weights) ----
        ln_kernel<<<NWIN, 256>>>(G, GN, g_norm_w, g_norm_b);
        tf32gemm_kernel<<<gg(2048, 1024), 256>>>(X, WC_kvx, KVX, nullptr, nullptr, 2048, 1024, 512, 1024, 0);
        smallgemm_kernel<<<4,  1024>>>(GN, g_Wq,  QG,  nullptr, nullptr, 16, 512,  512, 512,  0);
        smallgemm_kernel<<<8,  1024>>>(GN, g_Wkv, KVG, nullptr, nullptr, 16, 1024, 512, 1024, 0);
        global_attn_kernel<<<dim3(16, 8), 256>>>(QG, KVG, KVX, GO);
        smallgemm_kernel<<<4,  1024>>>(GO, g_Wo, G, g_bo, G, 16, 512, 512, 512, 0);
        ln_kernel<<<NWIN, 256>>>(G, GN, gff_norm_w, gff_norm_b);
        smallgemm_kernel<<<16, 1024>>>(GN, gff_W1, GH, gff_b1, nullptr, 16, 2048, 512,  2048, 1);
        smallgemm_kernel<<<4,  1024>>>(GH, gff_W2, G,  gff_b2, G,       16, 512,  2048, 512,  0);

        // ---- local windowed attention ----
        CVT(WC_q,  la_Wq  + (size_t)l * 512 * 512,  512 * 512);
        CVT(WC_kv, la_Wkv + (size_t)l * 512 * 1024, 512 * 1024);
        CVT(WC_wo, la_Wo  + (size_t)l * 512 * 512,  512 * 512);
        ln_kernel<<<NTOK, 256>>>(X, XN, la_norm_w + l * 512, la_norm_b + l * 512);
        tf32gemm_kernel<<<gg(2048, 512), 256>>>(XN, WC_q,  Q, nullptr, nullptr, 2048, 512, 512, 512,  0);
        tf32gemm_kernel<<<gg(2048, 512), 256>>>(XN, WC_kv, K, nullptr, nullptr, 2048, 512, 512, 1024, 0);
        smallgemm_kernel<<<8, 1024>>>(G, la_Wkv + (size_t)l * 512 * 1024, GKV, nullptr, nullptr, 15, 1024, 512, 1024, 0);
        rotary_kernel<<<NTOK, 256>>>(Q, K);
        local_attn_kernel<<<dim3(16, 8), 128, 73216>>>(Q, K, GKV, AO);
        tf32gemm_kernel<<<gg(2048, 512), 256>>>(AO, WC_wo, X, la_bo + l * 512, X, 2048, 512, 512, 512, 0);

        // ---- local FF ----
        CVT(WC_ff1, lff_W1 + (size_t)l * 512 * 2048, 512 * 2048);
        CVT(WC_ff2, lff_W2 + (size_t)l * 2048 * 512, 2048 * 512);
        ln_kernel<<<NTOK, 256>>>(X, XN, lff_norm_w + l * 512, lff_norm_b + l * 512);
        tf32gemm_kernel<<<gg(2048, 2048), 256>>>(XN, WC_ff1, H, lff_b1 + l * 2048, nullptr, 2048, 2048, 512,  2048, 1);
        tf32gemm_kernel<<<gg(2048, 512),  256>>>(H,  WC_ff2, X, lff_b2 + l * 512,  X,       2048, 512,  2048, 512,  0);
    }

    // ---- output head ----
    CVT(WC, out_W, 512 * 32000);
    ln_kernel<<<NTOK, 256>>>(X, XN, out_norm_w, out_norm_b);
    tf32gemm_kernel<<<gg(2048, 32000), 256>>>(XN, WC, (float*)d_out, out_b, nullptr,
                                              2048, 32000, 512, 32000, 0);
}

// round 8
// speedup vs baseline: 1.3352x; 1.1581x over previous
#include <cuda_runtime.h>
#include <math.h>
#include <stdint.h>

// ---------------- model constants ----------------
#define DMODEL 512
#define NTOK   2048
#define NWIN   16
#define WSZ    128
#define NHEAD  8
#define DHEAD  64
#define FFDIM  2048

// ---------------- scratch (no allocs allowed) ----------------
__device__ alignas(128) float g_X  [NTOK * DMODEL];
__device__ alignas(128) float g_XN [NTOK * DMODEL];
__device__ alignas(128) float g_Q  [NTOK * DMODEL];
__device__ alignas(128) float g_K  [NTOK * DMODEL];
__device__ alignas(128) float g_KVX[NTOK * 2 * DMODEL];
__device__ alignas(128) float g_H  [NTOK * FFDIM];
__device__ alignas(128) float g_AO [NTOK * DMODEL];
__device__ alignas(128) float g_G  [NWIN * DMODEL];
__device__ alignas(128) float g_GN [NWIN * DMODEL];
__device__ alignas(128) float g_QG [NWIN * DMODEL];
__device__ alignas(128) float g_KVG[NWIN * 2 * DMODEL];
__device__ alignas(128) float g_GO [NWIN * DMODEL];
__device__ alignas(128) float g_GH [NWIN * FFDIM];
__device__ alignas(128) float g_GKV[NWIN * 2 * DMODEL];
__device__ alignas(128) float g_WC [512 * 32000];     // tf32-converted weights
__device__ alignas(128) float g_PS [4 * 2048 * 512];  // split-K partials (16 MB)

// ---------------- embedding gather ----------------
__global__ void embed_kernel(const int* __restrict__ tokens,
                             const float* __restrict__ emb,
                             float* __restrict__ X)
{
    int row = blockIdx.x;
    int d   = threadIdx.x;
    X[row * DMODEL + d] = emb[(size_t)tokens[row] * DMODEL + d];
}

// ---------------- window mean + pos emb ----------------
__global__ void winmean_kernel(const float* __restrict__ X,
                               const float* __restrict__ gpos,
                               float* __restrict__ G)
{
    int w = blockIdx.x;
    int d = threadIdx.x;
    float s = 0.f;
    for (int i = 0; i < WSZ; i++)
        s += X[(w * WSZ + i) * DMODEL + d];
    G[w * DMODEL + d] = s * (1.f / 128.f) + gpos[w * DMODEL + d];
}

// ---------------- layernorm ----------------
__global__ void ln_kernel(const float* __restrict__ in, float* __restrict__ out,
                          const float* __restrict__ w, const float* __restrict__ b)
{
    __shared__ float sh[8];
    __shared__ float stat;
    int row = blockIdx.x;
    int tid = threadIdx.x;
    const float* r = in + (size_t)row * DMODEL;
    float x0 = r[tid], x1 = r[tid + 256];

    float v = x0 + x1;
    for (int o = 16; o; o >>= 1) v += __shfl_down_sync(0xffffffffu, v, o);
    if ((tid & 31) == 0) sh[tid >> 5] = v;
    __syncthreads();
    if (tid == 0) {
        float t = 0.f;
        for (int i = 0; i < 8; i++) t += sh[i];
        stat = t * (1.f / 512.f);
    }
    __syncthreads();
    float mu = stat;
    float d0 = x0 - mu, d1 = x1 - mu;
    __syncthreads();
    v = d0 * d0 + d1 * d1;
    for (int o = 16; o; o >>= 1) v += __shfl_down_sync(0xffffffffu, v, o);
    if ((tid & 31) == 0) sh[tid >> 5] = v;
    __syncthreads();
    if (tid == 0) {
        float t = 0.f;
        for (int i = 0; i < 8; i++) t += sh[i];
        stat = t * (1.f / 512.f);
    }
    __syncthreads();
    float rstd = rsqrtf(stat + 1e-5f);
    out[(size_t)row * DMODEL + tid]       = d0 * rstd * w[tid]       + b[tid];
    out[(size_t)row * DMODEL + tid + 256] = d1 * rstd * w[tid + 256] + b[tid + 256];
}

// ---------------- tf32 helpers ----------------
__device__ __forceinline__ float to_tf32(float x)
{
    float r;
    asm("cvt.rna.tf32.f32 %0, %1;" : "=f"(r) : "f"(x));
    return r;
}

__device__ __forceinline__ void mma_tf32(float* c, const uint32_t* a, const uint32_t* b)
{
    asm volatile(
        "mma.sync.aligned.m16n8k8.row.col.f32.tf32.tf32.f32 "
        "{%0,%1,%2,%3}, {%4,%5,%6,%7}, {%8,%9}, {%0,%1,%2,%3};"
        : "+f"(c[0]), "+f"(c[1]), "+f"(c[2]), "+f"(c[3])
        : "r"(a[0]), "r"(a[1]), "r"(a[2]), "r"(a[3]), "r"(b[0]), "r"(b[1]));
}

__device__ __forceinline__ void cp_async16(uint32_t dst, const void* src)
{
    asm volatile("cp.async.ca.shared.global [%0], [%1], 16;" :: "r"(dst), "l"(src));
}
__device__ __forceinline__ void cp_commit() { asm volatile("cp.async.commit_group;"); }
__device__ __forceinline__ void cp_wait0()  { asm volatile("cp.async.wait_group 0;"); }

// ---------------- weight tf32 pre-convert (elementwise, n % 1024 == 0) ----------------
__global__ void tf32cvt_kernel(const float4* __restrict__ src, float4* __restrict__ dst)
{
    int i = blockIdx.x * 256 + threadIdx.x;
    float4 v = src[i];
    dst[i] = make_float4(to_tf32(v.x), to_tf32(v.y), to_tf32(v.z), to_tf32(v.w));
}

// ---------------- split-K reduce: C = [res +] maybe_gelu(sum_s P[s] + bias) ----------------
__global__ void reduceK_kernel(const float* __restrict__ P, float* __restrict__ C,
                               const float* __restrict__ bias, const float* __restrict__ res,
                               int MN, int N, int S, int gelu_flag)
{
    int i = (blockIdx.x * 256 + threadIdx.x) * 4;
    float4 a = *reinterpret_cast<const float4*>(P + i);
    for (int s = 1; s < S; s++) {
        float4 b = *reinterpret_cast<const float4*>(P + (size_t)s * MN + i);
        a.x += b.x; a.y += b.y; a.z += b.z; a.w += b.w;
    }
    int col = i % N;
    if (bias) {
        a.x += bias[col]; a.y += bias[col + 1]; a.z += bias[col + 2]; a.w += bias[col + 3];
    }
    if (gelu_flag) {
        a.x = 0.5f * a.x * (1.f + erff(a.x * 0.70710678118654752f));
        a.y = 0.5f * a.y * (1.f + erff(a.y * 0.70710678118654752f));
        a.z = 0.5f * a.z * (1.f + erff(a.z * 0.70710678118654752f));
        a.w = 0.5f * a.w * (1.f + erff(a.w * 0.70710678118654752f));
    }
    if (res) {
        float4 r4 = *reinterpret_cast<const float4*>(res + i);
        a.x += r4.x; a.y += r4.y; a.z += r4.z; a.w += r4.w;
    }
    *reinterpret_cast<float4*>(C + i) = a;
}

// ---------------- tf32 tensor-core GEMM (M%128==0, N%128==0, klen%16==0) ----------------
// B pre-converted tf32, row stride ldb. A fp32, row stride lda; column window
// [z*klen, (z+1)*klen) per blockIdx.z (split-K); C += z*M*N (partials when z>0 used).
// A-smem swizzle: offset = buf*2080 + g*1040 + r*8 + 2*(c ^ (r&3) ^ ((r>>2)&1)) (+hi)
//  -> STS.64 and fragment LDS.64 both conflict-free per 16-lane phase.
#define KT 16
#define SMS 136
__global__ void __launch_bounds__(256, 2) tf32gemm_kernel(
    const float* __restrict__ A, const float* __restrict__ B, float* __restrict__ C,
    const float* __restrict__ bias, const float* __restrict__ res,
    int M, int N, int klen, int lda, int ldb, int gelu_flag)
{
    __shared__ float AswF[2 * 2080];      // [buf][g(pad 1040)][row*8 + slot]
    __shared__ float Bs[2][KT][SMS];

    const int tid  = threadIdx.x;
    const int lane = tid & 31, warp = tid >> 5;
    const int wm = (warp & 1) * 64;
    const int wn = (warp >> 1) * 32;
    const int crow0 = blockIdx.y * 128, ccol0 = blockIdx.x * 128;
    const int kz = blockIdx.z;

    const int a_r = tid >> 1, a_g = tid & 1;
    const int a_r3 = a_r & 3;
    const int a_b  = (a_r >> 2) & 1;
    const int b_r = tid >> 4, b_c = (tid & 15) * 8;

    const float* Ag = A + (size_t)(crow0 + a_r) * lda + (size_t)kz * klen + a_g * 8;
    const float* Bg = B + (size_t)((size_t)kz * klen + b_r) * ldb + ccol0 + b_c;
    C += (size_t)kz * M * N;

    const uint32_t bs0 = (uint32_t)__cvta_generic_to_shared(&Bs[0][b_r][b_c]);
    const uint32_t bs1 = (uint32_t)__cvta_generic_to_shared(&Bs[1][b_r][b_c]);

    // fragment slot offset: 2*((lane&3) ^ (q&3) ^ ((q>>2)&1)), q = lane>>2
    const int so = 2 * ((lane & 3) ^ ((lane >> 2) & 3) ^ ((lane >> 4) & 1));

    float acc[4][4][4];
#pragma unroll
    for (int i = 0; i < 4; i++)
#pragma unroll
        for (int j = 0; j < 4; j++)
#pragma unroll
            for (int k = 0; k < 4; k++) acc[i][j][k] = 0.f;

#define STAGEA(buf, v0, v1) do {                                                    \
    float* _d = AswF + (buf) * 2080 + a_g * 1040 + a_r * 8;                         \
    *reinterpret_cast<float2*>(_d + 2*(0 ^ a_r3 ^ a_b)) = make_float2(to_tf32((v0).x), to_tf32((v1).x)); \
    *reinterpret_cast<float2*>(_d + 2*(1 ^ a_r3 ^ a_b)) = make_float2(to_tf32((v0).y), to_tf32((v1).y)); \
    *reinterpret_cast<float2*>(_d + 2*(2 ^ a_r3 ^ a_b)) = make_float2(to_tf32((v0).z), to_tf32((v1).z)); \
    *reinterpret_cast<float2*>(_d + 2*(3 ^ a_r3 ^ a_b)) = make_float2(to_tf32((v0).w), to_tf32((v1).w)); \
} while (0)

    const int nk = klen / KT;   // >= 2 at all call sites

    // ---- stage tile 0 ----
    {
        float4 av0 = *reinterpret_cast<const float4*>(Ag);
        float4 av1 = *reinterpret_cast<const float4*>(Ag + 4);
        STAGEA(0, av0, av1);
        cp_async16(bs0,      Bg);
        cp_async16(bs0 + 16, Bg + 4);
        cp_commit();
    }
    cp_wait0();
    __syncthreads();

    for (int kt = 0; kt < nk; kt++) {
        const int cur = kt & 1, nxt = cur ^ 1;
        const bool more = (kt + 1 < nk);

        float4 av0, av1;
        if (more) {
            const float* Bp = Bg + (size_t)(kt + 1) * KT * ldb;
            uint32_t bd = nxt ? bs1 : bs0;
            cp_async16(bd,      Bp);
            cp_async16(bd + 16, Bp + 4);
            cp_commit();
            const float* Ap = Ag + (kt + 1) * KT;
            av0 = *reinterpret_cast<const float4*>(Ap);
            av1 = *reinterpret_cast<const float4*>(Ap + 4);
        }

#pragma unroll
        for (int kk = 0; kk < KT; kk += 8) {
            const int g = kk >> 3;
            const float* abase = AswF + cur * 2080 + g * 1040;
            uint32_t af[4][4], bf[4][2];
            const int kc = kk + (lane & 3);
#pragma unroll
            for (int am = 0; am < 4; am++) {
                const int r = wm + am * 16 + (lane >> 2);
                float2 p0 = *reinterpret_cast<const float2*>(abase + r * 8 + so);
                float2 p1 = *reinterpret_cast<const float2*>(abase + (r + 8) * 8 + so);
                af[am][0] = __float_as_uint(p0.x);
                af[am][1] = __float_as_uint(p1.x);
                af[am][2] = __float_as_uint(p0.y);
                af[am][3] = __float_as_uint(p1.y);
            }
#pragma unroll
            for (int bn = 0; bn < 4; bn++) {
                const int cc = wn + bn * 8 + (lane >> 2);
                bf[bn][0] = __float_as_uint(Bs[cur][kc][cc]);
                bf[bn][1] = __float_as_uint(Bs[cur][kc + 4][cc]);
            }
#pragma unroll
            for (int am = 0; am < 4; am++)
#pragma unroll
                for (int bn = 0; bn < 4; bn++)
                    mma_tf32(acc[am][bn], af[am], bf[bn]);
        }

        if (more) {
            STAGEA(nxt, av0, av1);
            cp_wait0();
            __syncthreads();
        }
    }

    // ---- epilogue ----
#pragma unroll
    for (int am = 0; am < 4; am++) {
        const int r0 = crow0 + wm + am * 16 + (lane >> 2);
#pragma unroll
        for (int bn = 0; bn < 4; bn++) {
            const int c0 = ccol0 + wn + bn * 8 + (lane & 3) * 2;
            float v0 = acc[am][bn][0], v1 = acc[am][bn][1];
            float v2 = acc[am][bn][2], v3 = acc[am][bn][3];
            if (bias) {
                float b0 = bias[c0], b1 = bias[c0 + 1];
                v0 += b0; v1 += b1; v2 += b0; v3 += b1;
            }
            if (gelu_flag) {
                v0 = 0.5f * v0 * (1.f + erff(v0 * 0.70710678118654752f));
                v1 = 0.5f * v1 * (1.f + erff(v1 * 0.70710678118654752f));
                v2 = 0.5f * v2 * (1.f + erff(v2 * 0.70710678118654752f));
                v3 = 0.5f * v3 * (1.f + erff(v3 * 0.70710678118654752f));
            }
            size_t i0 = (size_t)r0 * N + c0;
            size_t i1 = (size_t)(r0 + 8) * N + c0;
            if (res) {
                v0 += res[i0]; v1 += res[i0 + 1];
                v2 += res[i1]; v3 += res[i1 + 1];
            }
            *reinterpret_cast<float2*>(C + i0) = make_float2(v0, v1);
            *reinterpret_cast<float2*>(C + i1) = make_float2(v2, v3);
        }
    }
}

// ---------------- small-M GEMM (M<=16), fp32, split-K within block ----------------
#define SG_KC 256
__global__ void __launch_bounds__(1024, 1) smallgemm_kernel(
    const float* __restrict__ A, const float* __restrict__ B, float* __restrict__ C,
    const float* __restrict__ bias, const float* __restrict__ res,
    int M, int N, int K, int ldb, int gelu_flag)
{
    __shared__ float As[2][16][SG_KC];
    __shared__ float Ps[16][128];
    const int tid  = threadIdx.x;
    const int col  = blockIdx.x * 128 + (tid & 127);
    const int grp  = tid >> 7;
    const int half = grp >> 2;
    const int rg   = grp & 3;
    const int Kh   = K >> 1;

    float acc[4] = {0.f, 0.f, 0.f, 0.f};
    const float* Bp = B + (size_t)half * Kh * ldb + col;

    for (int kc = 0; kc < Kh; kc += SG_KC) {
        for (int idx = tid; idx < 2 * 16 * SG_KC; idx += 1024) {
            int h = idx >> 12;
            int r = (idx >> 8) & 15;
            int k = idx & (SG_KC - 1);
            As[h][r][k] = (r < M) ? A[(size_t)r * K + h * Kh + kc + k] : 0.f;
        }
        __syncthreads();
#pragma unroll 1
        for (int k0 = 0; k0 < SG_KC; k0 += 16) {
            float bv[16];
#pragma unroll
            for (int u = 0; u < 16; u++)
                bv[u] = Bp[(size_t)(kc + k0 + u) * ldb];
#pragma unroll
            for (int u = 0; u < 16; u++) {
#pragma unroll
                for (int r = 0; r < 4; r++)
                    acc[r] = fmaf(As[half][rg * 4 + r][k0 + u], bv[u], acc[r]);
            }
        }
        __syncthreads();
    }

    if (half == 1) {
#pragma unroll
        for (int r = 0; r < 4; r++)
            Ps[rg * 4 + r][tid & 127] = acc[r];
    }
    __syncthreads();
    if (half == 0) {
#pragma unroll
        for (int r = 0; r < 4; r++) {
            int gr = rg * 4 + r;
            if (gr >= M) continue;
            float v = acc[r] + Ps[gr][tid & 127];
            if (bias) v += bias[col];
            if (gelu_flag) v = 0.5f * v * (1.f + erff(v * 0.70710678118654752f));
            size_t idx = (size_t)gr * N + col;
            if (res) v += res[idx];
            C[idx] = v;
        }
    }
}

// ---------------- rotary embedding ----------------
__global__ void rotary_kernel(float* __restrict__ Q, float* __restrict__ K)
{
    int i = blockIdx.x;
    int t = threadIdx.x;
    int h = t >> 5, d = t & 31;
    float inv = 1.f / powf(10000.f, (float)(2 * d) / 64.f);
    float ang = (float)i * inv;
    float s, c;
    sincosf(ang, &s, &c);
    int base = i * DMODEL + h * DHEAD + d;
    float a = Q[base], b2 = Q[base + 32];
    Q[base]      = a * c - b2 * s;
    Q[base + 32] = b2 * c + a * s;
    a = K[base]; b2 = K[base + 32];
    K[base]      = a * c - b2 * s;
    K[base + 32] = b2 * c + a * s;
}

// ---------------- global-token attention ----------------
__global__ void global_attn_kernel(const float* __restrict__ QG,
                                   const float* __restrict__ KVG,
                                   const float* __restrict__ KVX,
                                   float* __restrict__ GO)
{
    __shared__ float q[64];
    __shared__ float lg[129];
    int w = blockIdx.x, h = blockIdx.y;
    int tid = threadIdx.x;
    if (tid < 64) q[tid] = QG[w * DMODEL + h * DHEAD + tid];
    __syncthreads();
    if (tid < 129) {
        const float* kp = (tid == 0)
            ? (KVG + (size_t)w * 1024 + h * DHEAD)
            : (KVX + (size_t)(w * WSZ + tid - 1) * 1024 + h * DHEAD);
        float dt = 0.f;
#pragma unroll
        for (int d = 0; d < 64; d++) dt = fmaf(q[d], kp[d], dt);
        lg[tid] = dt * 0.125f;
    }
    __syncthreads();
    float m = -1e30f;
    for (int j = 0; j < 129; j++) m = fmaxf(m, lg[j]);
    float s = 0.f;
    for (int j = 0; j < 129; j++) s += expf(lg[j] - m);
    if (tid < 64) {
        float acc = 0.f;
        for (int j = 0; j < 129; j++) {
            float p = expf(lg[j] - m);
            float v = (j == 0)
                ? KVG[(size_t)w * 1024 + 512 + h * DHEAD + tid]
                : KVX[(size_t)(w * WSZ + j - 1) * 1024 + 512 + h * DHEAD + tid];
            acc = fmaf(p, v, acc);
        }
        GO[w * DMODEL + h * DHEAD + tid] = acc / s;
    }
}

// ---------------- local windowed attention (two-pass) ----------------
__global__ void local_attn_kernel(const float* __restrict__ Q,
                                  const float* __restrict__ K,
                                  const float* __restrict__ GKV,
                                  float* __restrict__ AO)
{
    extern __shared__ float sm[];
    float* sk  = sm;                 // [271][64]
    float* sgv = sm + 271 * 64;      // [15][64]
    int w = blockIdx.x, h = blockIdx.y;
    int tid = threadIdx.x;           // 128

    for (int idx = tid; idx < 15 * 64; idx += 128) {
        int j = idx >> 6, d = idx & 63;
        sk[idx]  = GKV[(size_t)j * 1024 + h * DHEAD + d];
        sgv[idx] = GKV[(size_t)j * 1024 + 512 + h * DHEAD + d];
    }
    for (int idx = tid; idx < 256 * 64; idx += 128) {
        int c = idx >> 6, d = idx & 63;
        int t = (w - 1) * WSZ + c;
        sk[15 * 64 + idx] = (t >= 0) ? K[(size_t)t * DMODEL + h * DHEAD + d] : 0.f;
    }
    __syncthreads();

    const int i = tid;
    float q[64];
    const float* qp = Q + (size_t)(w * WSZ + i) * DMODEL + h * DHEAD;
#pragma unroll
    for (int d = 0; d < 64; d++) q[d] = qp[d];

    const int jend = 15 + i + 128;

    float m = -1e30f;
    for (int j = 0; j < w; j++) {
        const float* kp = sk + j * 64;
        float dt = 0.f;
#pragma unroll
        for (int d = 0; d < 64; d++) dt = fmaf(q[d], kp[d], dt);
        m = fmaxf(m, dt * 0.125f);
    }
    for (int j = 15; j <= jend; j++) {
        const float* kp = sk + j * 64;
        float dt = 0.f;
#pragma unroll
        for (int d = 0; d < 64; d++) dt = fmaf(q[d], kp[d], dt);
        m = fmaxf(m, dt * 0.125f);
    }

    float s = 0.f;
    float acc[64];
#pragma unroll
    for (int d = 0; d < 64; d++) acc[d] = 0.f;
    for (int j = 0; j < w; j++) {
        const float* kp = sk + j * 64;
        float dt = 0.f;
#pragma unroll
        for (int d = 0; d < 64; d++) dt = fmaf(q[d], kp[d], dt);
        float e = expf(dt * 0.125f - m);
        s += e;
        const float* vp = sgv + j * 64;
#pragma unroll
        for (int d = 0; d < 64; d++) acc[d] = fmaf(e, vp[d], acc[d]);
    }
    for (int j = 15; j <= jend; j++) {
        const float* kp = sk + j * 64;
        float dt = 0.f;
#pragma unroll
        for (int d = 0; d < 64; d++) dt = fmaf(q[d], kp[d], dt);
        float e = expf(dt * 0.125f - m);
        s += e;
#pragma unroll
        for (int d = 0; d < 64; d++) acc[d] = fmaf(e, kp[d], acc[d]);
    }
    float inv = 1.f / s;
    float* op = AO + (size_t)(w * WSZ + i) * DMODEL + h * DHEAD;
#pragma unroll
    for (int d = 0; d < 64; d++) op[d] = acc[d] * inv;
}

// ---------------- host orchestration ----------------
extern "C" void kernel_launch(void* const* d_in, const int* in_sizes, int n_in,
                              void* d_out, int out_size)
{
    const int*   tokens     = (const int*)  d_in[0];
    const float* tok_emb    = (const float*)d_in[1];
    const float* gpos_emb   = (const float*)d_in[2];
    const float* g_norm_w   = (const float*)d_in[3];
    const float* g_norm_b   = (const float*)d_in[4];
    const float* g_Wq       = (const float*)d_in[5];
    const float* g_Wkv      = (const float*)d_in[6];
    const float* g_Wo       = (const float*)d_in[7];
    const float* g_bo       = (const float*)d_in[8];
    const float* gff_norm_w = (const float*)d_in[9];
    const float* gff_norm_b = (const float*)d_in[10];
    const float* gff_W1     = (const float*)d_in[11];
    const float* gff_b1     = (const float*)d_in[12];
    const float* gff_W2     = (const float*)d_in[13];
    const float* gff_b2     = (const float*)d_in[14];
    const float* la_norm_w  = (const float*)d_in[15];
    const float* la_norm_b  = (const float*)d_in[16];
    const float* la_Wq      = (const float*)d_in[17];
    const float* la_Wkv     = (const float*)d_in[18];
    const float* la_Wo      = (const float*)d_in[19];
    const float* la_bo      = (const float*)d_in[20];
    const float* lff_norm_w = (const float*)d_in[21];
    const float* lff_norm_b = (const float*)d_in[22];
    const float* lff_W1     = (const float*)d_in[23];
    const float* lff_b1     = (const float*)d_in[24];
    const float* lff_W2     = (const float*)d_in[25];
    const float* lff_b2     = (const float*)d_in[26];
    const float* out_norm_w = (const float*)d_in[27];
    const float* out_norm_b = (const float*)d_in[28];
    const float* out_W      = (const float*)d_in[29];
    const float* out_b      = (const float*)d_in[30];

    float *X, *XN, *Q, *K, *KVX, *H, *AO, *G, *GN, *QG, *KVG, *GO, *GH, *GKV, *WC, *PS;
    cudaGetSymbolAddress((void**)&X,   g_X);
    cudaGetSymbolAddress((void**)&XN,  g_XN);
    cudaGetSymbolAddress((void**)&Q,   g_Q);
    cudaGetSymbolAddress((void**)&K,   g_K);
    cudaGetSymbolAddress((void**)&KVX, g_KVX);
    cudaGetSymbolAddress((void**)&H,   g_H);
    cudaGetSymbolAddress((void**)&AO,  g_AO);
    cudaGetSymbolAddress((void**)&G,   g_G);
    cudaGetSymbolAddress((void**)&GN,  g_GN);
    cudaGetSymbolAddress((void**)&QG,  g_QG);
    cudaGetSymbolAddress((void**)&KVG, g_KVG);
    cudaGetSymbolAddress((void**)&GO,  g_GO);
    cudaGetSymbolAddress((void**)&GH,  g_GH);
    cudaGetSymbolAddress((void**)&GKV, g_GKV);
    cudaGetSymbolAddress((void**)&WC,  g_WC);
    cudaGetSymbolAddress((void**)&PS,  g_PS);

    cudaFuncSetAttribute(local_attn_kernel,
                         cudaFuncAttributeMaxDynamicSharedMemorySize, 73216);

    float* WC_kvx = WC;                    // 512*1024
    float* WC_q   = WC + 512 * 1024;       // 512*512
    float* WC_kv  = WC + 512 * 1536;       // 512*1024
    float* WC_wo  = WC + 512 * 2560;       // 512*512
    float* WC_ff1 = WC + 512 * 3072;       // 512*2048
    float* WC_ff2 = WC + 512 * 5120;       // 2048*512

#define CVT(dst, src, n) tf32cvt_kernel<<<(n) / 1024, 256>>>((const float4*)(src), (float4*)(dst))

    embed_kernel<<<NTOK, DMODEL>>>(tokens, tok_emb, X);
    winmean_kernel<<<NWIN, DMODEL>>>(X, gpos_emb, G);
    CVT(WC_kvx, g_Wkv, 512 * 1024);        // shared across layers, converted once

    for (int l = 0; l < 2; l++) {
        // ---- global-token transformer (shared weights) ----
        ln_kernel<<<NWIN, 256>>>(G, GN, g_norm_w, g_norm_b);
        // KVX: split-K x2 -> 256 blocks, then reduce
        tf32gemm_kernel<<<dim3(8, 16, 2), 256>>>(X, WC_kvx, PS, nullptr, nullptr,
                                                 2048, 1024, 256, 512, 1024, 0);
        reduceK_kernel<<<2048, 256>>>(PS, KVX, nullptr, nullptr, 2048 * 1024, 1024, 2, 0);
        smallgemm_kernel<<<4,  1024>>>(GN, g_Wq,  QG,  nullptr, nullptr, 16, 512,  512, 512,  0);
        smallgemm_kernel<<<8,  1024>>>(GN, g_Wkv, KVG, nullptr, nullptr, 16, 1024, 512, 1024, 0);
        global_attn_kernel<<<dim3(16, 8), 256>>>(QG, KVG, KVX, GO);
        smallgemm_kernel<<<4,  1024>>>(GO, g_Wo, G, g_bo, G, 16, 512, 512, 512, 0);
        ln_kernel<<<NWIN, 256>>>(G, GN, gff_norm_w, gff_norm_b);
        smallgemm_kernel<<<16, 1024>>>(GN, gff_W1, GH, gff_b1, nullptr, 16, 2048, 512,  2048, 1);
        smallgemm_kernel<<<4,  1024>>>(GH, gff_W2, G,  gff_b2, G,       16, 512,  2048, 512,  0);

        // ---- local windowed attention ----
        CVT(WC_q,  la_Wq  + (size_t)l * 512 * 512,  512 * 512);
        CVT(WC_kv, la_Wkv + (size_t)l * 512 * 1024, 512 * 1024);
        CVT(WC_wo, la_Wo  + (size_t)l * 512 * 512,  512 * 512);
        ln_kernel<<<NTOK, 256>>>(X, XN, la_norm_w + l * 512, la_norm_b + l * 512);
        // Q: split-K x4 -> 256 blocks
        tf32gemm_kernel<<<dim3(4, 16, 4), 256>>>(XN, WC_q, PS, nullptr, nullptr,
                                                 2048, 512, 128, 512, 512, 0);
        reduceK_kernel<<<1024, 256>>>(PS, Q, nullptr, nullptr, 2048 * 512, 512, 4, 0);
        // K: split-K x4
        tf32gemm_kernel<<<dim3(4, 16, 4), 256>>>(XN, WC_kv, PS, nullptr, nullptr,
                                                 2048, 512, 128, 512, 1024, 0);
        reduceK_kernel<<<1024, 256>>>(PS, K, nullptr, nullptr, 2048 * 512, 512, 4, 0);
        smallgemm_kernel<<<8, 1024>>>(G, la_Wkv + (size_t)l * 512 * 1024, GKV, nullptr, nullptr, 15, 1024, 512, 1024, 0);
        rotary_kernel<<<NTOK, 256>>>(Q, K);
        local_attn_kernel<<<dim3(16, 8), 128, 73216>>>(Q, K, GKV, AO);
        // Wo: split-K x4, reduce applies bias + residual
        tf32gemm_kernel<<<dim3(4, 16, 4), 256>>>(AO, WC_wo, PS, nullptr, nullptr,
                                                 2048, 512, 128, 512, 512, 0);
        reduceK_kernel<<<1024, 256>>>(PS, X, la_bo + l * 512, X, 2048 * 512, 512, 4, 0);

        // ---- local FF ----
        CVT(WC_ff1, lff_W1 + (size_t)l * 512 * 2048, 512 * 2048);
        CVT(WC_ff2, lff_W2 + (size_t)l * 2048 * 512, 2048 * 512);
        ln_kernel<<<NTOK, 256>>>(X, XN, lff_norm_w + l * 512, lff_norm_b + l * 512);
        tf32gemm_kernel<<<dim3(16, 16, 1), 256>>>(XN, WC_ff1, H, lff_b1 + l * 2048, nullptr,
                                                  2048, 2048, 512, 512, 2048, 1);
        // FF2: split-K x4 (chunks of 512), reduce applies bias + residual
        tf32gemm_kernel<<<dim3(4, 16, 4), 256>>>(H, WC_ff2, PS, nullptr, nullptr,
                                                 2048, 512, 512, 2048, 512, 0);
        reduceK_kernel<<<1024, 256>>>(PS, X, lff_b2 + l * 512, X, 2048 * 512, 512, 4, 0);
    }

    // ---- output head ----
    CVT(WC, out_W, 512 * 32000);
    ln_kernel<<<NTOK, 256>>>(X, XN, out_norm_w, out_norm_b);
    tf32gemm_kernel<<<dim3(250, 16, 1), 256>>>(XN, WC, (float*)d_out, out_b, nullptr,
                                               2048, 32000, 512, 512, 32000, 0);
}

// round 9
// speedup vs baseline: 1.3801x; 1.0336x over previous
#include <cuda_runtime.h>
#include <math.h>
#include <stdint.h>

// ---------------- model constants ----------------
#define DMODEL 512
#define NTOK   2048
#define NWIN   16
#define WSZ    128
#define NHEAD  8
#define DHEAD  64
#define FFDIM  2048

// ---------------- scratch (no allocs allowed) ----------------
__device__ alignas(128) float g_X  [NTOK * DMODEL];
__device__ alignas(128) float g_XN [NTOK * DMODEL];
__device__ alignas(128) float g_Q  [NTOK * DMODEL];
__device__ alignas(128) float g_K  [NTOK * DMODEL];
__device__ alignas(128) float g_KVX[NTOK * 2 * DMODEL];
__device__ alignas(128) float g_H  [NTOK * FFDIM];
__device__ alignas(128) float g_AO [NTOK * DMODEL];
__device__ alignas(128) float g_G  [NWIN * DMODEL];
__device__ alignas(128) float g_GN [NWIN * DMODEL];
__device__ alignas(128) float g_QG [NWIN * DMODEL];
__device__ alignas(128) float g_KVG[NWIN * 2 * DMODEL];
__device__ alignas(128) float g_GO [NWIN * DMODEL];
__device__ alignas(128) float g_GH [NWIN * FFDIM];
__device__ alignas(128) float g_GKV[NWIN * 2 * DMODEL];
__device__ alignas(128) float g_WC [512 * 32000];     // tf32-converted weights
__device__ alignas(128) float g_PS [4 * 2048 * 512];  // split-K partials (16 MB)

// ---------------- embedding gather ----------------
__global__ void embed_kernel(const int* __restrict__ tokens,
                             const float* __restrict__ emb,
                             float* __restrict__ X)
{
    int row = blockIdx.x;
    int d   = threadIdx.x;
    X[row * DMODEL + d] = emb[(size_t)tokens[row] * DMODEL + d];
}

// ---------------- window mean + pos emb ----------------
__global__ void winmean_kernel(const float* __restrict__ X,
                               const float* __restrict__ gpos,
                               float* __restrict__ G)
{
    int w = blockIdx.x;
    int d = threadIdx.x;
    float s = 0.f;
    for (int i = 0; i < WSZ; i++)
        s += X[(w * WSZ + i) * DMODEL + d];
    G[w * DMODEL + d] = s * (1.f / 128.f) + gpos[w * DMODEL + d];
}

// ---------------- layernorm ----------------
__global__ void ln_kernel(const float* __restrict__ in, float* __restrict__ out,
                          const float* __restrict__ w, const float* __restrict__ b)
{
    __shared__ float sh[8];
    __shared__ float stat;
    int row = blockIdx.x;
    int tid = threadIdx.x;
    const float* r = in + (size_t)row * DMODEL;
    float x0 = r[tid], x1 = r[tid + 256];

    float v = x0 + x1;
    for (int o = 16; o; o >>= 1) v += __shfl_down_sync(0xffffffffu, v, o);
    if ((tid & 31) == 0) sh[tid >> 5] = v;
    __syncthreads();
    if (tid == 0) {
        float t = 0.f;
        for (int i = 0; i < 8; i++) t += sh[i];
        stat = t * (1.f / 512.f);
    }
    __syncthreads();
    float mu = stat;
    float d0 = x0 - mu, d1 = x1 - mu;
    __syncthreads();
    v = d0 * d0 + d1 * d1;
    for (int o = 16; o; o >>= 1) v += __shfl_down_sync(0xffffffffu, v, o);
    if ((tid & 31) == 0) sh[tid >> 5] = v;
    __syncthreads();
    if (tid == 0) {
        float t = 0.f;
        for (int i = 0; i < 8; i++) t += sh[i];
        stat = t * (1.f / 512.f);
    }
    __syncthreads();
    float rstd = rsqrtf(stat + 1e-5f);
    out[(size_t)row * DMODEL + tid]       = d0 * rstd * w[tid]       + b[tid];
    out[(size_t)row * DMODEL + tid + 256] = d1 * rstd * w[tid + 256] + b[tid + 256];
}

// ---------------- tf32 helpers ----------------
__device__ __forceinline__ float to_tf32(float x)
{
    float r;
    asm("cvt.rna.tf32.f32 %0, %1;" : "=f"(r) : "f"(x));
    return r;
}

__device__ __forceinline__ void mma_tf32(float* c, const uint32_t* a, const uint32_t* b)
{
    asm volatile(
        "mma.sync.aligned.m16n8k8.row.col.f32.tf32.tf32.f32 "
        "{%0,%1,%2,%3}, {%4,%5,%6,%7}, {%8,%9}, {%0,%1,%2,%3};"
        : "+f"(c[0]), "+f"(c[1]), "+f"(c[2]), "+f"(c[3])
        : "r"(a[0]), "r"(a[1]), "r"(a[2]), "r"(a[3]), "r"(b[0]), "r"(b[1]));
}

__device__ __forceinline__ void cp_async16(uint32_t dst, const void* src)
{
    asm volatile("cp.async.ca.shared.global [%0], [%1], 16;" :: "r"(dst), "l"(src));
}
__device__ __forceinline__ void cp_commit() { asm volatile("cp.async.commit_group;"); }
__device__ __forceinline__ void cp_wait0()  { asm volatile("cp.async.wait_group 0;"); }
__device__ __forceinline__ void cp_wait1()  { asm volatile("cp.async.wait_group 1;"); }

// ---------------- weight tf32 pre-convert (elementwise, n % 1024 == 0) ----------------
__global__ void tf32cvt_kernel(const float4* __restrict__ src, float4* __restrict__ dst)
{
    int i = blockIdx.x * 256 + threadIdx.x;
    float4 v = src[i];
    dst[i] = make_float4(to_tf32(v.x), to_tf32(v.y), to_tf32(v.z), to_tf32(v.w));
}

// ---------------- split-K reduce: C = [res +] maybe_gelu(sum_s P[s] + bias) ----------------
__global__ void reduceK_kernel(const float* __restrict__ P, float* __restrict__ C,
                               const float* __restrict__ bias, const float* __restrict__ res,
                               int MN, int N, int S, int gelu_flag)
{
    int i = (blockIdx.x * 256 + threadIdx.x) * 4;
    float4 a = *reinterpret_cast<const float4*>(P + i);
    for (int s = 1; s < S; s++) {
        float4 b = *reinterpret_cast<const float4*>(P + (size_t)s * MN + i);
        a.x += b.x; a.y += b.y; a.z += b.z; a.w += b.w;
    }
    int col = i % N;
    if (bias) {
        a.x += bias[col]; a.y += bias[col + 1]; a.z += bias[col + 2]; a.w += bias[col + 3];
    }
    if (gelu_flag) {
        a.x = 0.5f * a.x * (1.f + erff(a.x * 0.70710678118654752f));
        a.y = 0.5f * a.y * (1.f + erff(a.y * 0.70710678118654752f));
        a.z = 0.5f * a.z * (1.f + erff(a.z * 0.70710678118654752f));
        a.w = 0.5f * a.w * (1.f + erff(a.w * 0.70710678118654752f));
    }
    if (res) {
        float4 r4 = *reinterpret_cast<const float4*>(res + i);
        a.x += r4.x; a.y += r4.y; a.z += r4.z; a.w += r4.w;
    }
    *reinterpret_cast<float4*>(C + i) = a;
}

// ---------------- tf32 tensor-core GEMM (M%128==0, N%128==0, klen%16==0) ----------------
// B pre-converted tf32, row stride ldb. A fp32, row stride lda; column window
// [z*klen, (z+1)*klen) per blockIdx.z (split-K); C += z*M*N (partials when z>0 used).
// A-smem swizzle: offset = buf*2080 + g*1040 + r*8 + 2*(c ^ (r&3) ^ ((r>>2)&1)) (+hi)
// B: 3-stage cp.async ring, wait_group 1 -> the just-committed tile is never waited on.
#define KT 16
#define SMS 136
__global__ void __launch_bounds__(256, 2) tf32gemm_kernel(
    const float* __restrict__ A, const float* __restrict__ B, float* __restrict__ C,
    const float* __restrict__ bias, const float* __restrict__ res,
    int M, int N, int klen, int lda, int ldb, int gelu_flag)
{
    __shared__ float AswF[2 * 2080];      // [buf][g(pad 1040)][row*8 + slot]
    __shared__ float Bs[3][KT][SMS];      // [stage][k][n]

    const int tid  = threadIdx.x;
    const int lane = tid & 31, warp = tid >> 5;
    const int wm = (warp & 1) * 64;
    const int wn = (warp >> 1) * 32;
    const int crow0 = blockIdx.y * 128, ccol0 = blockIdx.x * 128;
    const int kz = blockIdx.z;

    const int a_r = tid >> 1, a_g = tid & 1;
    const int a_r3 = a_r & 3;
    const int a_b  = (a_r >> 2) & 1;
    const int b_r = tid >> 4, b_c = (tid & 15) * 8;

    const float* Ag = A + (size_t)(crow0 + a_r) * lda + (size_t)kz * klen + a_g * 8;
    const float* Bg = B + (size_t)((size_t)kz * klen + b_r) * ldb + ccol0 + b_c;
    C += (size_t)kz * M * N;

    uint32_t bsa[3];
    bsa[0] = (uint32_t)__cvta_generic_to_shared(&Bs[0][b_r][b_c]);
    bsa[1] = (uint32_t)__cvta_generic_to_shared(&Bs[1][b_r][b_c]);
    bsa[2] = (uint32_t)__cvta_generic_to_shared(&Bs[2][b_r][b_c]);

    const int so = 2 * ((lane & 3) ^ ((lane >> 2) & 3) ^ ((lane >> 4) & 1));

    float acc[4][4][4];
#pragma unroll
    for (int i = 0; i < 4; i++)
#pragma unroll
        for (int j = 0; j < 4; j++)
#pragma unroll
            for (int k = 0; k < 4; k++) acc[i][j][k] = 0.f;

#define STAGEA(buf, v0, v1) do {                                                    \
    float* _d = AswF + (buf) * 2080 + a_g * 1040 + a_r * 8;                         \
    *reinterpret_cast<float2*>(_d + 2*(0 ^ a_r3 ^ a_b)) = make_float2(to_tf32((v0).x), to_tf32((v1).x)); \
    *reinterpret_cast<float2*>(_d + 2*(1 ^ a_r3 ^ a_b)) = make_float2(to_tf32((v0).y), to_tf32((v1).y)); \
    *reinterpret_cast<float2*>(_d + 2*(2 ^ a_r3 ^ a_b)) = make_float2(to_tf32((v0).z), to_tf32((v1).z)); \
    *reinterpret_cast<float2*>(_d + 2*(3 ^ a_r3 ^ a_b)) = make_float2(to_tf32((v0).w), to_tf32((v1).w)); \
} while (0)

    const int nk = klen / KT;   // >= 8 at all call sites

    // ---- preamble: stage A0; launch B0 and B1 ----
    {
        float4 av0 = *reinterpret_cast<const float4*>(Ag);
        float4 av1 = *reinterpret_cast<const float4*>(Ag + 4);
        STAGEA(0, av0, av1);
        cp_async16(bsa[0],      Bg);
        cp_async16(bsa[0] + 16, Bg + 4);
        cp_commit();
        const float* Bp = Bg + (size_t)KT * ldb;
        cp_async16(bsa[1],      Bp);
        cp_async16(bsa[1] + 16, Bp + 4);
        cp_commit();
    }
    cp_wait1();            // B0 complete (B1 in flight)
    __syncthreads();

    for (int kt = 0; kt < nk; kt++) {
        const int cur = kt & 1;
        const int s   = kt % 3;
        const bool more = (kt + 1 < nk);

        if (kt + 2 < nk) {
            const float* Bp = Bg + (size_t)(kt + 2) * KT * ldb;
            uint32_t bd = bsa[(kt + 2) % 3];
            cp_async16(bd,      Bp);
            cp_async16(bd + 16, Bp + 4);
            cp_commit();
        }

        float4 av0, av1;
        if (more) {
            const float* Ap = Ag + (kt + 1) * KT;
            av0 = *reinterpret_cast<const float4*>(Ap);
            av1 = *reinterpret_cast<const float4*>(Ap + 4);
        }

#pragma unroll
        for (int kk = 0; kk < KT; kk += 8) {
            const int g = kk >> 3;
            const float* abase = AswF + cur * 2080 + g * 1040;
            uint32_t af[4][4], bf[4][2];
            const int kc = kk + (lane & 3);
#pragma unroll
            for (int am = 0; am < 4; am++) {
                const int r = wm + am * 16 + (lane >> 2);
                float2 p0 = *reinterpret_cast<const float2*>(abase + r * 8 + so);
                float2 p1 = *reinterpret_cast<const float2*>(abase + (r + 8) * 8 + so);
                af[am][0] = __float_as_uint(p0.x);
                af[am][1] = __float_as_uint(p1.x);
                af[am][2] = __float_as_uint(p0.y);
                af[am][3] = __float_as_uint(p1.y);
            }
#pragma unroll
            for (int bn = 0; bn < 4; bn++) {
                const int cc = wn + bn * 8 + (lane >> 2);
                bf[bn][0] = __float_as_uint(Bs[s][kc][cc]);
                bf[bn][1] = __float_as_uint(Bs[s][kc + 4][cc]);
            }
#pragma unroll
            for (int am = 0; am < 4; am++)
#pragma unroll
                for (int bn = 0; bn < 4; bn++)
                    mma_tf32(acc[am][bn], af[am], bf[bn]);
        }

        if (more) {
            STAGEA(cur ^ 1, av0, av1);
            if (kt + 2 < nk) cp_wait1(); else cp_wait0();
            __syncthreads();
        }
    }

    // ---- epilogue ----
#pragma unroll
    for (int am = 0; am < 4; am++) {
        const int r0 = crow0 + wm + am * 16 + (lane >> 2);
#pragma unroll
        for (int bn = 0; bn < 4; bn++) {
            const int c0 = ccol0 + wn + bn * 8 + (lane & 3) * 2;
            float v0 = acc[am][bn][0], v1 = acc[am][bn][1];
            float v2 = acc[am][bn][2], v3 = acc[am][bn][3];
            if (bias) {
                float b0 = bias[c0], b1 = bias[c0 + 1];
                v0 += b0; v1 += b1; v2 += b0; v3 += b1;
            }
            if (gelu_flag) {
                v0 = 0.5f * v0 * (1.f + erff(v0 * 0.70710678118654752f));
                v1 = 0.5f * v1 * (1.f + erff(v1 * 0.70710678118654752f));
                v2 = 0.5f * v2 * (1.f + erff(v2 * 0.70710678118654752f));
                v3 = 0.5f * v3 * (1.f + erff(v3 * 0.70710678118654752f));
            }
            size_t i0 = (size_t)r0 * N + c0;
            size_t i1 = (size_t)(r0 + 8) * N + c0;
            if (res) {
                v0 += res[i0]; v1 += res[i0 + 1];
                v2 += res[i1]; v3 += res[i1 + 1];
            }
            *reinterpret_cast<float2*>(C + i0) = make_float2(v0, v1);
            *reinterpret_cast<float2*>(C + i1) = make_float2(v2, v3);
        }
    }
}

// ---------------- small-M GEMM (M<=16), fp32, 4-way in-block split-K ----------------
// 1024 threads = 128 cols x 4 k-quarters x 2 row-halves (8 rows each).
// Requires K % 256 == 0 (K = 512 or 2048 at all call sites).
#define SG4_CH 64
__global__ void __launch_bounds__(1024, 1) smallgemm_kernel(
    const float* __restrict__ A, const float* __restrict__ B, float* __restrict__ C,
    const float* __restrict__ bias, const float* __restrict__ res,
    int M, int N, int K, int ldb, int gelu_flag)
{
    __shared__ float As[4][16][SG4_CH];   // 16 KB
    __shared__ float Ps[3][16][128];      // 24 KB
    const int tid = threadIdx.x;
    const int cl  = tid & 127;
    const int col = blockIdx.x * 128 + cl;
    const int grp = tid >> 7;             // 0..7
    const int q   = grp >> 1;             // k-quarter 0..3
    const int rg  = grp & 1;              // row half
    const int Kq  = K >> 2;

    float acc[8] = {0.f, 0.f, 0.f, 0.f, 0.f, 0.f, 0.f, 0.f};
    const float* Bp = B + (size_t)q * Kq * ldb + col;

    for (int cc = 0; cc < Kq; cc += SG4_CH) {
        for (int idx = tid; idx < 4 * 16 * SG4_CH; idx += 1024) {
            int qq = idx >> 10;           // 16*64 per quarter
            int r  = (idx >> 6) & 15;
            int k  = idx & 63;
            As[qq][r][k] = (r < M) ? A[(size_t)r * K + qq * Kq + cc + k] : 0.f;
        }
        __syncthreads();
#pragma unroll 1
        for (int k0 = 0; k0 < SG4_CH; k0 += 16) {
            float bv[16];
#pragma unroll
            for (int u = 0; u < 16; u++)
                bv[u] = Bp[(size_t)(cc + k0 + u) * ldb];
#pragma unroll
            for (int u = 0; u < 16; u++) {
#pragma unroll
                for (int r = 0; r < 8; r++)
                    acc[r] = fmaf(As[q][rg * 8 + r][k0 + u], bv[u], acc[r]);
            }
        }
        __syncthreads();
    }

    if (q >= 1) {
#pragma unroll
        for (int r = 0; r < 8; r++)
            Ps[q - 1][rg * 8 + r][cl] = acc[r];
    }
    __syncthreads();
    if (q == 0) {
#pragma unroll
        for (int r = 0; r < 8; r++) {
            int gr = rg * 8 + r;
            if (gr >= M) continue;
            float v = acc[r] + Ps[0][gr][cl] + Ps[1][gr][cl] + Ps[2][gr][cl];
            if (bias) v += bias[col];
            if (gelu_flag) v = 0.5f * v * (1.f + erff(v * 0.70710678118654752f));
            size_t idx = (size_t)gr * N + col;
            if (res) v += res[idx];
            C[idx] = v;
        }
    }
}

// ---------------- rotary embedding ----------------
__global__ void rotary_kernel(float* __restrict__ Q, float* __restrict__ K)
{
    int i = blockIdx.x;
    int t = threadIdx.x;
    int h = t >> 5, d = t & 31;
    float inv = 1.f / powf(10000.f, (float)(2 * d) / 64.f);
    float ang = (float)i * inv;
    float s, c;
    sincosf(ang, &s, &c);
    int base = i * DMODEL + h * DHEAD + d;
    float a = Q[base], b2 = Q[base + 32];
    Q[base]      = a * c - b2 * s;
    Q[base + 32] = b2 * c + a * s;
    a = K[base]; b2 = K[base + 32];
    K[base]      = a * c - b2 * s;
    K[base + 32] = b2 * c + a * s;
}

// ---------------- global-token attention ----------------
__global__ void global_attn_kernel(const float* __restrict__ QG,
                                   const float* __restrict__ KVG,
                                   const float* __restrict__ KVX,
                                   float* __restrict__ GO)
{
    __shared__ float q[64];
    __shared__ float lg[129];
    int w = blockIdx.x, h = blockIdx.y;
    int tid = threadIdx.x;
    if (tid < 64) q[tid] = QG[w * DMODEL + h * DHEAD + tid];
    __syncthreads();
    if (tid < 129) {
        const float* kp = (tid == 0)
            ? (KVG + (size_t)w * 1024 + h * DHEAD)
            : (KVX + (size_t)(w * WSZ + tid - 1) * 1024 + h * DHEAD);
        float dt = 0.f;
#pragma unroll
        for (int d = 0; d < 64; d++) dt = fmaf(q[d], kp[d], dt);
        lg[tid] = dt * 0.125f;
    }
    __syncthreads();
    float m = -1e30f;
    for (int j = 0; j < 129; j++) m = fmaxf(m, lg[j]);
    float s = 0.f;
    for (int j = 0; j < 129; j++) s += expf(lg[j] - m);
    if (tid < 64) {
        float acc = 0.f;
        for (int j = 0; j < 129; j++) {
            float p = expf(lg[j] - m);
            float v = (j == 0)
                ? KVG[(size_t)w * 1024 + 512 + h * DHEAD + tid]
                : KVX[(size_t)(w * WSZ + j - 1) * 1024 + 512 + h * DHEAD + tid];
            acc = fmaf(p, v, acc);
        }
        GO[w * DMODEL + h * DHEAD + tid] = acc / s;
    }
}

// ---------------- local windowed attention (two-pass) ----------------
__global__ void local_attn_kernel(const float* __restrict__ Q,
                                  const float* __restrict__ K,
                                  const float* __restrict__ GKV,
                                  float* __restrict__ AO)
{
    extern __shared__ float sm[];
    float* sk  = sm;                 // [271][64]
    float* sgv = sm + 271 * 64;      // [15][64]
    int w = blockIdx.x, h = blockIdx.y;
    int tid = threadIdx.x;           // 128

    for (int idx = tid; idx < 15 * 64; idx += 128) {
        int j = idx >> 6, d = idx & 63;
        sk[idx]  = GKV[(size_t)j * 1024 + h * DHEAD + d];
        sgv[idx] = GKV[(size_t)j * 1024 + 512 + h * DHEAD + d];
    }
    for (int idx = tid; idx < 256 * 64; idx += 128) {
        int c = idx >> 6, d = idx & 63;
        int t = (w - 1) * WSZ + c;
        sk[15 * 64 + idx] = (t >= 0) ? K[(size_t)t * DMODEL + h * DHEAD + d] : 0.f;
    }
    __syncthreads();

    const int i = tid;
    float q[64];
    const float* qp = Q + (size_t)(w * WSZ + i) * DMODEL + h * DHEAD;
#pragma unroll
    for (int d = 0; d < 64; d++) q[d] = qp[d];

    const int jend = 15 + i + 128;

    float m = -1e30f;
    for (int j = 0; j < w; j++) {
        const float* kp = sk + j * 64;
        float dt = 0.f;
#pragma unroll
        for (int d = 0; d < 64; d++) dt = fmaf(q[d], kp[d], dt);
        m = fmaxf(m, dt * 0.125f);
    }
    for (int j = 15; j <= jend; j++) {
        const float* kp = sk + j * 64;
        float dt = 0.f;
#pragma unroll
        for (int d = 0; d < 64; d++) dt = fmaf(q[d], kp[d], dt);
        m = fmaxf(m, dt * 0.125f);
    }

    float s = 0.f;
    float acc[64];
#pragma unroll
    for (int d = 0; d < 64; d++) acc[d] = 0.f;
    for (int j = 0; j < w; j++) {
        const float* kp = sk + j * 64;
        float dt = 0.f;
#pragma unroll
        for (int d = 0; d < 64; d++) dt = fmaf(q[d], kp[d], dt);
        float e = expf(dt * 0.125f - m);
        s += e;
        const float* vp = sgv + j * 64;
#pragma unroll
        for (int d = 0; d < 64; d++) acc[d] = fmaf(e, vp[d], acc[d]);
    }
    for (int j = 15; j <= jend; j++) {
        const float* kp = sk + j * 64;
        float dt = 0.f;
#pragma unroll
        for (int d = 0; d < 64; d++) dt = fmaf(q[d], kp[d], dt);
        float e = expf(dt * 0.125f - m);
        s += e;
#pragma unroll
        for (int d = 0; d < 64; d++) acc[d] = fmaf(e, kp[d], acc[d]);
    }
    float inv = 1.f / s;
    float* op = AO + (size_t)(w * WSZ + i) * DMODEL + h * DHEAD;
#pragma unroll
    for (int d = 0; d < 64; d++) op[d] = acc[d] * inv;
}

// ---------------- host orchestration ----------------
extern "C" void kernel_launch(void* const* d_in, const int* in_sizes, int n_in,
                              void* d_out, int out_size)
{
    const int*   tokens     = (const int*)  d_in[0];
    const float* tok_emb    = (const float*)d_in[1];
    const float* gpos_emb   = (const float*)d_in[2];
    const float* g_norm_w   = (const float*)d_in[3];
    const float* g_norm_b   = (const float*)d_in[4];
    const float* g_Wq       = (const float*)d_in[5];
    const float* g_Wkv      = (const float*)d_in[6];
    const float* g_Wo       = (const float*)d_in[7];
    const float* g_bo       = (const float*)d_in[8];
    const float* gff_norm_w = (const float*)d_in[9];
    const float* gff_norm_b = (const float*)d_in[10];
    const float* gff_W1     = (const float*)d_in[11];
    const float* gff_b1     = (const float*)d_in[12];
    const float* gff_W2     = (const float*)d_in[13];
    const float* gff_b2     = (const float*)d_in[14];
    const float* la_norm_w  = (const float*)d_in[15];
    const float* la_norm_b  = (const float*)d_in[16];
    const float* la_Wq      = (const float*)d_in[17];
    const float* la_Wkv     = (const float*)d_in[18];
    const float* la_Wo      = (const float*)d_in[19];
    const float* la_bo      = (const float*)d_in[20];
    const float* lff_norm_w = (const float*)d_in[21];
    const float* lff_norm_b = (const float*)d_in[22];
    const float* lff_W1     = (const float*)d_in[23];
    const float* lff_b1     = (const float*)d_in[24];
    const float* lff_W2     = (const float*)d_in[25];
    const float* lff_b2     = (const float*)d_in[26];
    const float* out_norm_w = (const float*)d_in[27];
    const float* out_norm_b = (const float*)d_in[28];
    const float* out_W      = (const float*)d_in[29];
    const float* out_b      = (const float*)d_in[30];

    float *X, *XN, *Q, *K, *KVX, *H, *AO, *G, *GN, *QG, *KVG, *GO, *GH, *GKV, *WC, *PS;
    cudaGetSymbolAddress((void**)&X,   g_X);
    cudaGetSymbolAddress((void**)&XN,  g_XN);
    cudaGetSymbolAddress((void**)&Q,   g_Q);
    cudaGetSymbolAddress((void**)&K,   g_K);
    cudaGetSymbolAddress((void**)&KVX, g_KVX);
    cudaGetSymbolAddress((void**)&H,   g_H);
    cudaGetSymbolAddress((void**)&AO,  g_AO);
    cudaGetSymbolAddress((void**)&G,   g_G);
    cudaGetSymbolAddress((void**)&GN,  g_GN);
    cudaGetSymbolAddress((void**)&QG,  g_QG);
    cudaGetSymbolAddress((void**)&KVG, g_KVG);
    cudaGetSymbolAddress((void**)&GO,  g_GO);
    cudaGetSymbolAddress((void**)&GH,  g_GH);
    cudaGetSymbolAddress((void**)&GKV, g_GKV);
    cudaGetSymbolAddress((void**)&WC,  g_WC);
    cudaGetSymbolAddress((void**)&PS,  g_PS);

    cudaFuncSetAttribute(local_attn_kernel,
                         cudaFuncAttributeMaxDynamicSharedMemorySize, 73216);

    float* WC_kvx = WC;                    // 512*1024
    float* WC_q   = WC + 512 * 1024;       // 512*512
    float* WC_kv  = WC + 512 * 1536;       // 512*1024
    float* WC_wo  = WC + 512 * 2560;       // 512*512
    float* WC_ff1 = WC + 512 * 3072;       // 512*2048
    float* WC_ff2 = WC + 512 * 5120;       // 2048*512

#define CVT(dst, src, n) tf32cvt_kernel<<<(n) / 1024, 256>>>((const float4*)(src), (float4*)(dst))

    embed_kernel<<<NTOK, DMODEL>>>(tokens, tok_emb, X);
    winmean_kernel<<<NWIN, DMODEL>>>(X, gpos_emb, G);
    CVT(WC_kvx, g_Wkv, 512 * 1024);        // shared across layers, converted once

    for (int l = 0; l < 2; l++) {
        // ---- global-token transformer (shared weights) ----
        ln_kernel<<<NWIN, 256>>>(G, GN, g_norm_w, g_norm_b);
        // KVX: split-K x2 -> 256 blocks, then reduce
        tf32gemm_kernel<<<dim3(8, 16, 2), 256>>>(X, WC_kvx, PS, nullptr, nullptr,
                                                 2048, 1024, 256, 512, 1024, 0);
        reduceK_kernel<<<2048, 256>>>(PS, KVX, nullptr, nullptr, 2048 * 1024, 1024, 2, 0);
        smallgemm_kernel<<<4,  1024>>>(GN, g_Wq,  QG,  nullptr, nullptr, 16, 512,  512, 512,  0);
        smallgemm_kernel<<<8,  1024>>>(GN, g_Wkv, KVG, nullptr, nullptr, 16, 1024, 512, 1024, 0);
        global_attn_kernel<<<dim3(16, 8), 256>>>(QG, KVG, KVX, GO);
        smallgemm_kernel<<<4,  1024>>>(GO, g_Wo, G, g_bo, G, 16, 512, 512, 512, 0);
        ln_kernel<<<NWIN, 256>>>(G, GN, gff_norm_w, gff_norm_b);
        smallgemm_kernel<<<16, 1024>>>(GN, gff_W1, GH, gff_b1, nullptr, 16, 2048, 512,  2048, 1);
        smallgemm_kernel<<<4,  1024>>>(GH, gff_W2, G,  gff_b2, G,       16, 512,  2048, 512,  0);

        // ---- local windowed attention ----
        CVT(WC_q,  la_Wq  + (size_t)l * 512 * 512,  512 * 512);
        CVT(WC_kv, la_Wkv + (size_t)l * 512 * 1024, 512 * 1024);
        CVT(WC_wo, la_Wo  + (size_t)l * 512 * 512,  512 * 512);
        ln_kernel<<<NTOK, 256>>>(X, XN, la_norm_w + l * 512, la_norm_b + l * 512);
        // Q: split-K x4 -> 256 blocks
        tf32gemm_kernel<<<dim3(4, 16, 4), 256>>>(XN, WC_q, PS, nullptr, nullptr,
                                                 2048, 512, 128, 512, 512, 0);
        reduceK_kernel<<<1024, 256>>>(PS, Q, nullptr, nullptr, 2048 * 512, 512, 4, 0);
        // K: split-K x4
        tf32gemm_kernel<<<dim3(4, 16, 4), 256>>>(XN, WC_kv, PS, nullptr, nullptr,
                                                 2048, 512, 128, 512, 1024, 0);
        reduceK_kernel<<<1024, 256>>>(PS, K, nullptr, nullptr, 2048 * 512, 512, 4, 0);
        smallgemm_kernel<<<8, 1024>>>(G, la_Wkv + (size_t)l * 512 * 1024, GKV, nullptr, nullptr, 15, 1024, 512, 1024, 0);
        rotary_kernel<<<NTOK, 256>>>(Q, K);
        local_attn_kernel<<<dim3(16, 8), 128, 73216>>>(Q, K, GKV, AO);
        // Wo: split-K x4, reduce applies bias + residual
        tf32gemm_kernel<<<dim3(4, 16, 4), 256>>>(AO, WC_wo, PS, nullptr, nullptr,
                                                 2048, 512, 128, 512, 512, 0);
        reduceK_kernel<<<1024, 256>>>(PS, X, la_bo + l * 512, X, 2048 * 512, 512, 4, 0);

        // ---- local FF ----
        CVT(WC_ff1, lff_W1 + (size_t)l * 512 * 2048, 512 * 2048);
        CVT(WC_ff2, lff_W2 + (size_t)l * 2048 * 512, 2048 * 512);
        ln_kernel<<<NTOK, 256>>>(X, XN, lff_norm_w + l * 512, lff_norm_b + l * 512);
        tf32gemm_kernel<<<dim3(16, 16, 1), 256>>>(XN, WC_ff1, H, lff_b1 + l * 2048, nullptr,
                                                  2048, 2048, 512, 512, 2048, 1);
        // FF2: split-K x4 (chunks of 512), reduce applies bias + residual
        tf32gemm_kernel<<<dim3(4, 16, 4), 256>>>(H, WC_ff2, PS, nullptr, nullptr,
                                                 2048, 512, 512, 2048, 512, 0);
        reduceK_kernel<<<1024, 256>>>(PS, X, lff_b2 + l * 512, X, 2048 * 512, 512, 4, 0);
    }

    // ---- output head ----
    CVT(WC, out_W, 512 * 32000);
    ln_kernel<<<NTOK, 256>>>(X, XN, out_norm_w, out_norm_b);
    tf32gemm_kernel<<<dim3(250, 16, 1), 256>>>(XN, WC, (float*)d_out, out_b, nullptr,
                                               2048, 32000, 512, 512, 32000, 0);
}